// round 9
// baseline (speedup 1.0000x reference)
#include <cuda_runtime.h>
#include <math.h>
#include <stdint.h>

// Problem constants
#define NZ   256
#define NH   2048
#define NG   8192      // 4*NH gate rows
#define TT   256       // timesteps
#define KF4  (NH/4)    // 512 float4 per h-vector
#define PBLOCK 1024
#define UPB    16               // hidden units per block (16 warp-pairs)
#define GRID   (NH/UPB)         // 128 blocks
#define KH4    256              // uint4 per hh row (2048 weights)
#define KH4H   (KH4/2)          // half-row per warp (K-split)
#define BMAGIC 8421376.0f       // 2^23 + 32768 (biased-u16 offset)

// ---------------- device scratch (no allocations allowed) ----------------
__device__ float g_bias[4][NG];          // b_ih + b_hh per layer
__device__ float g_pre[TT * NG];         // per-layer precomputed ih gates (+bias), 8.4MB
__device__ float g_hsA[TT * NH];         // ping-pong hidden-sequence buffers
__device__ float g_hsB[TT * NH];
__device__ unsigned g_sense;             // broadcast word; even flips/launch -> replay-safe
__device__ unsigned g_flags[GRID * 32];  // per-block arrival flags, 128B apart

// quantized hh weights for all 4 layers, biased uint16 (q = round(w/s)+32768)
__device__ unsigned short q_hh[(size_t)4 * NG * NH];   // 134 MB
__device__ float s_hh[4 * NG];           // per-row dequant scales

// HW tanh (max err ~1e-5, well inside budget); sigmoid via exact identity
__device__ __forceinline__ float tanh_fast(float x) {
    float y;
    asm("tanh.approx.f32 %0, %1;" : "=f"(y) : "f"(x));
    return y;
}
__device__ __forceinline__ float sigf(float x) {
    return fmaf(0.5f, tanh_fast(0.5f * x), 0.5f);
}

// biased-u16 -> float WITHOUT bias removal: value = 2^23 + 32768 + q_signed
#define CVR_LO(v) (__uint_as_float(__byte_perm((v), 0x4B000000u, 0x7410)))
#define CVR_HI(v) (__uint_as_float(__byte_perm((v), 0x4B000000u, 0x7632)))

// accumulate one uint4 (8 raw weights) against 8 values (two float4) + bias fold
#define ACC8RAW(acc, w, lo, hi, vs)                   \
    do {                                              \
        acc = fmaf(CVR_LO((w).x), (lo).x, acc);       \
        acc = fmaf(CVR_HI((w).x), (lo).y, acc);       \
        acc = fmaf(CVR_LO((w).y), (lo).z, acc);       \
        acc = fmaf(CVR_HI((w).y), (lo).w, acc);       \
        acc = fmaf(CVR_LO((w).z), (hi).x, acc);       \
        acc = fmaf(CVR_HI((w).z), (hi).y, acc);       \
        acc = fmaf(CVR_LO((w).w), (hi).z, acc);       \
        acc = fmaf(CVR_HI((w).w), (hi).w, acc);       \
        acc = fmaf(-BMAGIC, (vs), acc);               \
    } while (0)

// ---------------- prologue: summed biases ----------------
__global__ void bias_kernel(const float* __restrict__ bi0, const float* __restrict__ bh0,
                            const float* __restrict__ bir, const float* __restrict__ bhr) {
    int idx = blockIdx.x * blockDim.x + threadIdx.x;   // 4*NG threads
    if (idx < 4 * NG) {
        int l = idx >> 13;
        int r = idx & (NG - 1);
        float v = (l == 0) ? (bi0[r] + bh0[r])
                           : (bir[(size_t)(l - 1) * NG + r] + bhr[(size_t)(l - 1) * NG + r]);
        g_bias[l][r] = v;
    }
}

// ---------------- prologue: quantize the 4 hh matrices to biased u16 ----------------
__global__ void quant_kernel(const float* __restrict__ whh0,
                             const float* __restrict__ whhr) {
    int gw   = (blockIdx.x * blockDim.x + threadIdx.x) >> 5;
    int lane = threadIdx.x & 31;
    int nw   = (gridDim.x * blockDim.x) >> 5;
    for (int r = gw; r < 4 * NG; r += nw) {
        int l  = r >> 13;
        int rr = r & (NG - 1);
        const float* src = (l == 0) ? whh0 + (size_t)rr * NH
                                    : whhr + ((size_t)(l - 1) * NG + rr) * NH;
        const float4* s4 = (const float4*)src;
        float m = 0.f;
        #pragma unroll 4
        for (int i = lane; i < KF4; i += 32) {
            float4 v = s4[i];
            m = fmaxf(m, fmaxf(fmaxf(fabsf(v.x), fabsf(v.y)), fmaxf(fabsf(v.z), fabsf(v.w))));
        }
        #pragma unroll
        for (int o = 16; o; o >>= 1) m = fmaxf(m, __shfl_xor_sync(0xffffffffu, m, o));
        float qs = (m > 0.f) ? 32767.0f / m : 0.f;
        if (lane == 0) s_hh[r] = (m > 0.f) ? m / 32767.0f : 0.f;
        ushort4* d4 = (ushort4*)(q_hh + (size_t)r * NH);
        #pragma unroll 4
        for (int i = lane; i < KF4; i += 32) {
            float4 v = s4[i];
            ushort4 o;
            o.x = (unsigned short)(__float2int_rn(v.x * qs) + 32768);
            o.y = (unsigned short)(__float2int_rn(v.y * qs) + 32768);
            o.z = (unsigned short)(__float2int_rn(v.z * qs) + 32768);
            o.w = (unsigned short)(__float2int_rn(v.w * qs) + 32768);
            d4[i] = o;
        }
    }
}

// ---------------- prologue: g_pre[t][r] = bias0[r] for all t (layer0 default) -------
__global__ void prefill_kernel() {
    int t = blockIdx.x;
    for (int r = threadIdx.x; r < NG; r += blockDim.x)
        g_pre[(size_t)t * NG + r] = g_bias[0][r];
}

// ---------------- prologue: overwrite t=0 with z @ W_ih0^T + bias0 ----------------
__global__ void pre0_kernel(const float* __restrict__ wih0, const float* __restrict__ z) {
    int gw   = (blockIdx.x * blockDim.x + threadIdx.x) >> 5;
    int lane = threadIdx.x & 31;
    int nw   = (gridDim.x * blockDim.x) >> 5;
    for (int row = gw; row < NG; row += nw) {
        const float* wr = wih0 + (size_t)row * NZ;
        float s = 0.f;
        for (int k = lane; k < NZ; k += 32) s += wr[k] * z[k];
        #pragma unroll
        for (int o = 16; o; o >>= 1) s += __shfl_xor_sync(0xffffffffu, s, o);
        if (lane == 0) g_pre[row] = s + g_bias[0][row];
    }
}

// ---------------- per-layer ih GEMM: pre[t][row] = X[t]·W[row] + bias[row] ----------
// X: [TT][NH] fp32, W: [NG][NH] fp32. 128x128 tile, BK=16, 256 threads, 8x8 micro.
#define GBK 16
__global__ void __launch_bounds__(256, 1)
gemm_pre_kernel(const float* __restrict__ X,
                const float* __restrict__ Wf,
                const float* __restrict__ bias) {
    __shared__ float Xs[GBK][132];   // [k][t], padded stride
    __shared__ float Ws[GBK][132];   // [k][row]
    const int tid = threadIdx.x;
    const int rb  = blockIdx.x * 128;   // gate-row base
    const int tb  = blockIdx.y * 128;   // t base
    const int tx  = tid & 15, ty = tid >> 4;

    float acc[8][8];
    #pragma unroll
    for (int i = 0; i < 8; ++i)
        #pragma unroll
        for (int j = 0; j < 8; ++j) acc[i][j] = 0.f;

    float4 px[2], pw[2];
    // prefetch first K-tile (coalesced: 4 consecutive threads cover one row's 64B)
    #pragma unroll
    for (int r = 0; r < 2; ++r) {
        int idx = tid + r * 256;            // 0..511
        int tt  = idx >> 2;                 // row/t index 0..127
        int k4  = idx & 3;                  // 0..3 (float4 within 16-wide K tile)
        px[r] = *(const float4*)(X  + (size_t)(tb + tt) * NH + k4 * 4);
        pw[r] = *(const float4*)(Wf + (size_t)(rb + tt) * NH + k4 * 4);
    }

    for (int kk = 0; kk < NH; kk += GBK) {
        __syncthreads();   // previous tile's compute done
        #pragma unroll
        for (int r = 0; r < 2; ++r) {
            int idx = tid + r * 256;
            int tt  = idx >> 2;
            int k0  = (idx & 3) * 4;
            Xs[k0 + 0][tt] = px[r].x; Xs[k0 + 1][tt] = px[r].y;
            Xs[k0 + 2][tt] = px[r].z; Xs[k0 + 3][tt] = px[r].w;
            Ws[k0 + 0][tt] = pw[r].x; Ws[k0 + 1][tt] = pw[r].y;
            Ws[k0 + 2][tt] = pw[r].z; Ws[k0 + 3][tt] = pw[r].w;
        }
        __syncthreads();
        if (kk + GBK < NH) {    // prefetch next tile (overlaps compute)
            #pragma unroll
            for (int r = 0; r < 2; ++r) {
                int idx = tid + r * 256;
                int tt  = idx >> 2;
                int k4  = idx & 3;
                px[r] = *(const float4*)(X  + (size_t)(tb + tt) * NH + kk + GBK + k4 * 4);
                pw[r] = *(const float4*)(Wf + (size_t)(rb + tt) * NH + kk + GBK + k4 * 4);
            }
        }
        #pragma unroll
        for (int k = 0; k < GBK; ++k) {
            float4 x0 = *(const float4*)&Xs[k][ty * 8];
            float4 x1 = *(const float4*)&Xs[k][ty * 8 + 4];
            float4 w0 = *(const float4*)&Ws[k][tx * 8];
            float4 w1 = *(const float4*)&Ws[k][tx * 8 + 4];
            float xr[8] = {x0.x, x0.y, x0.z, x0.w, x1.x, x1.y, x1.z, x1.w};
            float wr[8] = {w0.x, w0.y, w0.z, w0.w, w1.x, w1.y, w1.z, w1.w};
            #pragma unroll
            for (int i = 0; i < 8; ++i)
                #pragma unroll
                for (int j = 0; j < 8; ++j)
                    acc[i][j] = fmaf(xr[i], wr[j], acc[i][j]);
        }
    }

    const float4 b0 = *(const float4*)&bias[rb + tx * 8];
    const float4 b1 = *(const float4*)&bias[rb + tx * 8 + 4];
    #pragma unroll
    for (int i = 0; i < 8; ++i) {
        float* cp = g_pre + (size_t)(tb + ty * 8 + i) * NG + rb + tx * 8;
        float4 v0 = make_float4(acc[i][0] + b0.x, acc[i][1] + b0.y,
                                acc[i][2] + b0.z, acc[i][3] + b0.w);
        float4 v1 = make_float4(acc[i][4] + b1.x, acc[i][5] + b1.y,
                                acc[i][6] + b1.z, acc[i][7] + b1.w);
        *(float4*)cp       = v0;
        *(float4*)(cp + 4) = v1;
    }
}

// ---------------- flag-tree grid barrier: relaxed spins, release stores --------------
// NO atomics (avoids 128-way serialization at one L2 line) and NO acquire loads
// (avoids L1 invalidation -> pinned weights persist). Release stores order the
// h writes into L2 before the flag; all cross-block reads use __ldcg (L2-direct).
__device__ __forceinline__ void grid_barrier(unsigned& sense) {
    unsigned s = sense ^ 1u;
    sense = s;
    __syncthreads();                       // all out[] stores issued block-wide
    if (blockIdx.x == 0) {
        if (threadIdx.x == 0)
            asm volatile("st.release.gpu.global.u32 [%0], %1;"
                         :: "l"(&g_flags[0]), "r"(s) : "memory");
        if (threadIdx.x < GRID) {          // parallel poll: one flag per thread
            unsigned v;
            do {
                asm volatile("ld.relaxed.gpu.global.u32 %0, [%1];"
                             : "=r"(v) : "l"(&g_flags[threadIdx.x * 32]) : "memory");
            } while (v != s);
        }
        __syncthreads();                   // all flags observed
        if (threadIdx.x == 0)
            asm volatile("st.release.gpu.global.u32 [%0], %1;"
                         :: "l"(&g_sense), "r"(s) : "memory");
    } else {
        if (threadIdx.x == 0) {
            asm volatile("st.release.gpu.global.u32 [%0], %1;"
                         :: "l"(&g_flags[blockIdx.x * 32]), "r"(s) : "memory");
            unsigned v;
            do {
                asm volatile("ld.relaxed.gpu.global.u32 %0, [%1];"
                             : "=r"(v) : "l"(&g_sense) : "memory");
            } while (v != s);
        }
        __syncthreads();
    }
}

// ---------------- per-layer persistent step kernel (hh matvec only) ----------------
// 128 blocks x 1024 threads; each hidden unit owned by a warp PAIR (K-split).
// Gates i,f,g pinned in L1 via __ldg (196KB/block < L1); gate o streamed from L2
// via __ldcg (evict-normal in L2, L1-bypass). h staging + pre also L1-bypassed.
__global__ void __launch_bounds__(PBLOCK, 1)
lstm_layer_kernel(const unsigned short* __restrict__ Wq,  // layer hh weights (biased u16)
                  const float* __restrict__ scl,          // per-row scales [NG]
                  float* __restrict__ out) {              // [TT][NH] hidden out
    __shared__ float4 sh4[512];       // h_{t-1} (8 KB)
    __shared__ float comb[UPB][4];    // high-half partial gate sums

    const int tid  = threadIdx.x;
    const int lane = tid & 31;
    const int widx = tid >> 5;        // 0..31
    const int uw   = widx & 15;       // unit within block
    const int half = widx >> 4;       // K-half
    const int u    = blockIdx.x * UPB + uw;
    const uint4* W = (const uint4*)Wq + (size_t)u * KH4 + half * KH4H;
    const int GS   = NH * KH4;        // uint4 stride between gate blocks
    const int vb   = half * 256;      // float4 base of this half in sh4
    const bool epi = (half == 0) && (lane == 0);   // epilogue lane

    // loop-invariant dequant scales (registers, loaded once)
    const float sc0 = scl[u];
    const float sc1 = scl[NH + u];
    const float sc2 = scl[2 * NH + u];
    const float sc3 = scl[3 * NH + u];

    unsigned sense = 0;
    float c = 0.f;                    // cell state (low warp, lane 0)

    for (int t = 0; t < TT; ++t) {
        // prefetch pre-gate values (depend only on t) -- overlaps the dot loop
        float p0 = 0.f, p1 = 0.f, p2 = 0.f, p3 = 0.f;
        if (epi) {
            const float* pt = g_pre + (size_t)t * NG;
            p0 = __ldcg(pt + u);
            p1 = __ldcg(pt + NH + u);
            p2 = __ldcg(pt + 2 * NH + u);
            p3 = __ldcg(pt + 3 * NH + u);
        }
        if (tid < 512)
            sh4[tid] = (t > 0)
                ? __ldcg((const float4*)out + (size_t)(t - 1) * KF4 + tid)
                : make_float4(0.f, 0.f, 0.f, 0.f);
        __syncthreads();

        float a0 = 0.f, a1 = 0.f, a2 = 0.f, a3 = 0.f;
        #pragma unroll 2
        for (int j = lane; j < KH4H; j += 32) {
            const float4 lo = sh4[vb + 2 * j], hi = sh4[vb + 2 * j + 1];
            const float vs = lo.x + lo.y + lo.z + lo.w
                           + hi.x + hi.y + hi.z + hi.w;
            uint4 w;
            w = __ldg (W + j);          ACC8RAW(a0, w, lo, hi, vs);   // L1-pinned
            w = __ldg (W + GS + j);     ACC8RAW(a1, w, lo, hi, vs);   // L1-pinned
            w = __ldg (W + 2 * GS + j); ACC8RAW(a2, w, lo, hi, vs);   // L1-pinned
            w = __ldcg(W + 3 * GS + j); ACC8RAW(a3, w, lo, hi, vs);   // L2 stream
        }
        #pragma unroll
        for (int o = 16; o; o >>= 1) {
            a0 += __shfl_xor_sync(0xffffffffu, a0, o);
            a1 += __shfl_xor_sync(0xffffffffu, a1, o);
            a2 += __shfl_xor_sync(0xffffffffu, a2, o);
            a3 += __shfl_xor_sync(0xffffffffu, a3, o);
        }
        if (half == 1 && lane == 0) {   // high warp publishes; low warp only READS
            comb[uw][0] = a0; comb[uw][1] = a1;
            comb[uw][2] = a2; comb[uw][3] = a3;
        }
        __syncthreads();

        if (epi) {
            a0 += comb[uw][0]; a1 += comb[uw][1];
            a2 += comb[uw][2]; a3 += comb[uw][3];
            float ig = fmaf(a0, sc0, p0);
            float fg = fmaf(a1, sc1, p1);
            float gg = fmaf(a2, sc2, p2);
            float og = fmaf(a3, sc3, p3);
            c = sigf(fg) * c + sigf(ig) * tanh_fast(gg);
            out[(size_t)t * NH + u] = sigf(og) * tanh_fast(c);
        }

        grid_barrier(sense);   // 256 flips per launch (even parity: replay-safe)
    }
}

// ---------------- epilogue: states[t] = h3[t] @ w_sp^T + b_sp ----------------
__global__ void proj_kernel(const float* __restrict__ wsp, const float* __restrict__ bsp,
                            float* __restrict__ out) {
    __shared__ float4 shh[KF4];
    const int t = blockIdx.x;
    const int tid = threadIdx.x;    // 256 threads
    const float4* h4 = (const float4*)g_hsB + (size_t)t * KF4;  // layer3 output in B
    shh[tid]       = h4[tid];
    shh[tid + 256] = h4[tid + 256];
    __syncthreads();
    const int widx = tid >> 5, lane = tid & 31;
    for (int o = widx; o < 64; o += 8) {
        const float4* wr = (const float4*)wsp + (size_t)o * KF4;
        float s = 0.f;
        #pragma unroll 4
        for (int i = lane; i < KF4; i += 32) {
            float4 w = __ldg(wr + i);
            float4 hv = shh[i];
            s += w.x * hv.x + w.y * hv.y + w.z * hv.z + w.w * hv.w;
        }
        #pragma unroll
        for (int off = 16; off; off >>= 1) s += __shfl_xor_sync(0xffffffffu, s, off);
        if (lane == 0) out[(size_t)t * 64 + o] = s + bsp[o];
    }
}

// ---------------- launch ----------------
extern "C" void kernel_launch(void* const* d_in, const int* in_sizes, int n_in,
                              void* d_out, int out_size) {
    const float* z      = (const float*)d_in[0];
    const float* w_ih0  = (const float*)d_in[1];
    const float* w_hh0  = (const float*)d_in[2];
    const float* b_ih0  = (const float*)d_in[3];
    const float* b_hh0  = (const float*)d_in[4];
    const float* w_ih_r = (const float*)d_in[5];
    const float* w_hh_r = (const float*)d_in[6];
    const float* b_ih_r = (const float*)d_in[7];
    const float* b_hh_r = (const float*)d_in[8];
    const float* w_sp   = (const float*)d_in[9];
    const float* b_sp   = (const float*)d_in[10];
    float* out = (float*)d_out;

    static unsigned short* q_hh_p = nullptr;
    static float* s_hh_p = nullptr;
    static float* bias_p = nullptr;
    static float* hsA_p = nullptr;
    static float* hsB_p = nullptr;
    if (!q_hh_p) {
        cudaGetSymbolAddress((void**)&q_hh_p, q_hh);
        cudaGetSymbolAddress((void**)&s_hh_p, s_hh);
        cudaGetSymbolAddress((void**)&bias_p, g_bias);
        cudaGetSymbolAddress((void**)&hsA_p, g_hsA);
        cudaGetSymbolAddress((void**)&hsB_p, g_hsB);
        // minimal smem carveout -> maximal L1 for pinned weights
        cudaFuncSetAttribute(lstm_layer_kernel,
                             cudaFuncAttributePreferredSharedMemoryCarveout, 10);
    }

    dim3 ggrid(NG / 128, TT / 128);   // 64 x 2 = 128 blocks (one wave)

    bias_kernel<<<64, 512>>>(b_ih0, b_hh0, b_ih_r, b_hh_r);
    quant_kernel<<<448, 512>>>(w_hh0, w_hh_r);
    prefill_kernel<<<TT, 1024>>>();
    pre0_kernel<<<128, 256>>>(w_ih0, z);

    // layer 0 -> hsA
    lstm_layer_kernel<<<GRID, PBLOCK>>>(q_hh_p, s_hh_p, hsA_p);
    // layer 1: pre = hsA @ w_ih_r[0]^T + bias1 ; -> hsB
    gemm_pre_kernel<<<ggrid, 256>>>(hsA_p, w_ih_r, bias_p + 1 * NG);
    lstm_layer_kernel<<<GRID, PBLOCK>>>(q_hh_p + (size_t)1 * NG * NH, s_hh_p + 1 * NG, hsB_p);
    // layer 2
    gemm_pre_kernel<<<ggrid, 256>>>(hsB_p, w_ih_r + (size_t)1 * NG * NH, bias_p + 2 * NG);
    lstm_layer_kernel<<<GRID, PBLOCK>>>(q_hh_p + (size_t)2 * NG * NH, s_hh_p + 2 * NG, hsA_p);
    // layer 3
    gemm_pre_kernel<<<ggrid, 256>>>(hsA_p, w_ih_r + (size_t)2 * NG * NH, bias_p + 3 * NG);
    lstm_layer_kernel<<<GRID, PBLOCK>>>(q_hh_p + (size_t)3 * NG * NH, s_hh_p + 3 * NG, hsB_p);

    proj_kernel<<<TT, 256>>>(w_sp, b_sp, out);
}

// round 10
// speedup vs baseline: 1.1251x; 1.1251x over previous
#include <cuda_runtime.h>
#include <math.h>
#include <stdint.h>

// Problem constants
#define NZ   256
#define NH   2048
#define NG   8192      // 4*NH gate rows
#define TT   256       // timesteps
#define KF4  (NH/4)    // 512 float4 per h-vector
#define PBLOCK 1024
#define UPB    16               // hidden units per block (16 warp-pairs)
#define GRID   (NH/UPB)         // 128 blocks
#define KH4    256              // uint4 per hh row (2048 weights)
#define KH4H   (KH4/2)          // half-row per warp (K-split)
#define BMAGIC 8421376.0f       // 2^23 + 32768 (biased-u16 offset)

// dynamic smem layout: [0,64K) gate-g weights; [64K,72K) sh4; [72K,+256) comb
#define SMW_BYTES  (UPB * KH4 * 16)            // 65536
#define SH4_OFF    (SMW_BYTES)                 // 65536
#define COMB_OFF   (SMW_BYTES + 8192)          // 73728
#define SMEM_DYN   (COMB_OFF + UPB * 4 * 4)    // 73984 bytes

// ---------------- device scratch (no allocations allowed) ----------------
__device__ float g_bias[4][NG];          // b_ih + b_hh per layer
__device__ float g_pre[TT * NG];         // per-layer precomputed ih gates (+bias), 8.4MB
__device__ float g_hsA[TT * NH];         // ping-pong hidden-sequence buffers
__device__ float g_hsB[TT * NH];
__device__ unsigned g_count;             // grid barrier (returns to 0)
__device__ unsigned g_sense;             // parity; 256 flips/launch (even) -> replay-safe

// quantized hh weights for all 4 layers, biased uint16 (q = round(w/s)+32768)
__device__ unsigned short q_hh[(size_t)4 * NG * NH];   // 134 MB
__device__ float s_hh[4 * NG];           // per-row dequant scales

// HW tanh (max err ~1e-5, well inside budget); sigmoid via exact identity
__device__ __forceinline__ float tanh_fast(float x) {
    float y;
    asm("tanh.approx.f32 %0, %1;" : "=f"(y) : "f"(x));
    return y;
}
__device__ __forceinline__ float sigf(float x) {
    return fmaf(0.5f, tanh_fast(0.5f * x), 0.5f);
}

// biased-u16 -> float WITHOUT bias removal: value = 2^23 + 32768 + q_signed
#define CVR_LO(v) (__uint_as_float(__byte_perm((v), 0x4B000000u, 0x7410)))
#define CVR_HI(v) (__uint_as_float(__byte_perm((v), 0x4B000000u, 0x7632)))

// accumulate one uint4 (8 raw weights) against 8 values (two float4) + bias fold
#define ACC8RAW(acc, w, lo, hi, vs)                   \
    do {                                              \
        acc = fmaf(CVR_LO((w).x), (lo).x, acc);       \
        acc = fmaf(CVR_HI((w).x), (lo).y, acc);       \
        acc = fmaf(CVR_LO((w).y), (lo).z, acc);       \
        acc = fmaf(CVR_HI((w).y), (lo).w, acc);       \
        acc = fmaf(CVR_LO((w).z), (hi).x, acc);       \
        acc = fmaf(CVR_HI((w).z), (hi).y, acc);       \
        acc = fmaf(CVR_LO((w).w), (hi).z, acc);       \
        acc = fmaf(CVR_HI((w).w), (hi).w, acc);       \
        acc = fmaf(-BMAGIC, (vs), acc);               \
    } while (0)

// ---------------- prologue: summed biases ----------------
__global__ void bias_kernel(const float* __restrict__ bi0, const float* __restrict__ bh0,
                            const float* __restrict__ bir, const float* __restrict__ bhr) {
    int idx = blockIdx.x * blockDim.x + threadIdx.x;   // 4*NG threads
    if (idx < 4 * NG) {
        int l = idx >> 13;
        int r = idx & (NG - 1);
        float v = (l == 0) ? (bi0[r] + bh0[r])
                           : (bir[(size_t)(l - 1) * NG + r] + bhr[(size_t)(l - 1) * NG + r]);
        g_bias[l][r] = v;
    }
}

// ---------------- prologue: quantize the 4 hh matrices to biased u16 ----------------
__global__ void quant_kernel(const float* __restrict__ whh0,
                             const float* __restrict__ whhr) {
    int gw   = (blockIdx.x * blockDim.x + threadIdx.x) >> 5;
    int lane = threadIdx.x & 31;
    int nw   = (gridDim.x * blockDim.x) >> 5;
    for (int r = gw; r < 4 * NG; r += nw) {
        int l  = r >> 13;
        int rr = r & (NG - 1);
        const float* src = (l == 0) ? whh0 + (size_t)rr * NH
                                    : whhr + ((size_t)(l - 1) * NG + rr) * NH;
        const float4* s4 = (const float4*)src;
        float m = 0.f;
        #pragma unroll 4
        for (int i = lane; i < KF4; i += 32) {
            float4 v = s4[i];
            m = fmaxf(m, fmaxf(fmaxf(fabsf(v.x), fabsf(v.y)), fmaxf(fabsf(v.z), fabsf(v.w))));
        }
        #pragma unroll
        for (int o = 16; o; o >>= 1) m = fmaxf(m, __shfl_xor_sync(0xffffffffu, m, o));
        float qs = (m > 0.f) ? 32767.0f / m : 0.f;
        if (lane == 0) s_hh[r] = (m > 0.f) ? m / 32767.0f : 0.f;
        ushort4* d4 = (ushort4*)(q_hh + (size_t)r * NH);
        #pragma unroll 4
        for (int i = lane; i < KF4; i += 32) {
            float4 v = s4[i];
            ushort4 o;
            o.x = (unsigned short)(__float2int_rn(v.x * qs) + 32768);
            o.y = (unsigned short)(__float2int_rn(v.y * qs) + 32768);
            o.z = (unsigned short)(__float2int_rn(v.z * qs) + 32768);
            o.w = (unsigned short)(__float2int_rn(v.w * qs) + 32768);
            d4[i] = o;
        }
    }
}

// ---------------- prologue: g_pre[t][r] = bias0[r] for all t (layer0 default) -------
__global__ void prefill_kernel() {
    int t = blockIdx.x;
    for (int r = threadIdx.x; r < NG; r += blockDim.x)
        g_pre[(size_t)t * NG + r] = g_bias[0][r];
}

// ---------------- prologue: overwrite t=0 with z @ W_ih0^T + bias0 ----------------
__global__ void pre0_kernel(const float* __restrict__ wih0, const float* __restrict__ z) {
    int gw   = (blockIdx.x * blockDim.x + threadIdx.x) >> 5;
    int lane = threadIdx.x & 31;
    int nw   = (gridDim.x * blockDim.x) >> 5;
    for (int row = gw; row < NG; row += nw) {
        const float* wr = wih0 + (size_t)row * NZ;
        float s = 0.f;
        for (int k = lane; k < NZ; k += 32) s += wr[k] * z[k];
        #pragma unroll
        for (int o = 16; o; o >>= 1) s += __shfl_xor_sync(0xffffffffu, s, o);
        if (lane == 0) g_pre[row] = s + g_bias[0][row];
    }
}

// ---------------- per-layer ih GEMM: pre[t][row] = X[t]·W[row] + bias[row] ----------
// X: [TT][NH] fp32, W: [NG][NH] fp32. 128x128 tile, BK=16, 256 threads, 8x8 micro.
#define GBK 16
__global__ void __launch_bounds__(256, 1)
gemm_pre_kernel(const float* __restrict__ X,
                const float* __restrict__ Wf,
                const float* __restrict__ bias) {
    __shared__ float Xs[GBK][132];   // [k][t], padded stride
    __shared__ float Ws[GBK][132];   // [k][row]
    const int tid = threadIdx.x;
    const int rb  = blockIdx.x * 128;   // gate-row base
    const int tb  = blockIdx.y * 128;   // t base
    const int tx  = tid & 15, ty = tid >> 4;

    float acc[8][8];
    #pragma unroll
    for (int i = 0; i < 8; ++i)
        #pragma unroll
        for (int j = 0; j < 8; ++j) acc[i][j] = 0.f;

    float4 px[2], pw[2];
    // prefetch first K-tile (coalesced: 4 consecutive threads cover one row's 64B)
    #pragma unroll
    for (int r = 0; r < 2; ++r) {
        int idx = tid + r * 256;            // 0..511
        int tt  = idx >> 2;                 // row/t index 0..127
        int k4  = idx & 3;                  // 0..3 (float4 within 16-wide K tile)
        px[r] = *(const float4*)(X  + (size_t)(tb + tt) * NH + k4 * 4);
        pw[r] = *(const float4*)(Wf + (size_t)(rb + tt) * NH + k4 * 4);
    }

    for (int kk = 0; kk < NH; kk += GBK) {
        __syncthreads();   // previous tile's compute done
        #pragma unroll
        for (int r = 0; r < 2; ++r) {
            int idx = tid + r * 256;
            int tt  = idx >> 2;
            int k0  = (idx & 3) * 4;
            Xs[k0 + 0][tt] = px[r].x; Xs[k0 + 1][tt] = px[r].y;
            Xs[k0 + 2][tt] = px[r].z; Xs[k0 + 3][tt] = px[r].w;
            Ws[k0 + 0][tt] = pw[r].x; Ws[k0 + 1][tt] = pw[r].y;
            Ws[k0 + 2][tt] = pw[r].z; Ws[k0 + 3][tt] = pw[r].w;
        }
        __syncthreads();
        if (kk + GBK < NH) {    // prefetch next tile (overlaps compute)
            #pragma unroll
            for (int r = 0; r < 2; ++r) {
                int idx = tid + r * 256;
                int tt  = idx >> 2;
                int k4  = idx & 3;
                px[r] = *(const float4*)(X  + (size_t)(tb + tt) * NH + kk + GBK + k4 * 4);
                pw[r] = *(const float4*)(Wf + (size_t)(rb + tt) * NH + kk + GBK + k4 * 4);
            }
        }
        #pragma unroll
        for (int k = 0; k < GBK; ++k) {
            float4 x0 = *(const float4*)&Xs[k][ty * 8];
            float4 x1 = *(const float4*)&Xs[k][ty * 8 + 4];
            float4 w0 = *(const float4*)&Ws[k][tx * 8];
            float4 w1 = *(const float4*)&Ws[k][tx * 8 + 4];
            float xr[8] = {x0.x, x0.y, x0.z, x0.w, x1.x, x1.y, x1.z, x1.w};
            float wr[8] = {w0.x, w0.y, w0.z, w0.w, w1.x, w1.y, w1.z, w1.w};
            #pragma unroll
            for (int i = 0; i < 8; ++i)
                #pragma unroll
                for (int j = 0; j < 8; ++j)
                    acc[i][j] = fmaf(xr[i], wr[j], acc[i][j]);
        }
    }

    const float4 b0 = *(const float4*)&bias[rb + tx * 8];
    const float4 b1 = *(const float4*)&bias[rb + tx * 8 + 4];
    #pragma unroll
    for (int i = 0; i < 8; ++i) {
        float* cp = g_pre + (size_t)(tb + ty * 8 + i) * NG + rb + tx * 8;
        float4 v0 = make_float4(acc[i][0] + b0.x, acc[i][1] + b0.y,
                                acc[i][2] + b0.z, acc[i][3] + b0.w);
        float4 v1 = make_float4(acc[i][4] + b1.x, acc[i][5] + b1.y,
                                acc[i][6] + b1.z, acc[i][7] + b1.w);
        *(float4*)cp       = v0;
        *(float4*)(cp + 4) = v1;
    }
}

// ---------------- R8 grid barrier: single atomic arrival + relaxed spin -------------
// atom.release orders this block's prior stores; spin is ld.relaxed (L2 read,
// no L1 invalidate). Cross-block h data is read via __ldcg, so L1 holds only
// read-only weights, which legally persist across the barrier.
__device__ __forceinline__ void grid_barrier(unsigned& sense) {
    __syncthreads();
    if (threadIdx.x == 0) {
        unsigned s = sense ^ 1u;
        sense = s;
        unsigned old;
        asm volatile("atom.release.gpu.global.add.u32 %0, [%1], %2;"
                     : "=r"(old) : "l"(&g_count), "r"(1u) : "memory");
        if (old == (unsigned)(GRID - 1)) {
            asm volatile("st.relaxed.gpu.global.u32 [%0], %1;"
                         :: "l"(&g_count), "r"(0u) : "memory");
            asm volatile("st.release.gpu.global.u32 [%0], %1;"
                         :: "l"(&g_sense), "r"(s) : "memory");
        } else {
            unsigned v;
            do {
                asm volatile("ld.relaxed.gpu.global.u32 %0, [%1];"
                             : "=r"(v) : "l"(&g_sense) : "memory");
            } while (v != s);
        }
    }
    __syncthreads();
}

// ---------------- per-layer persistent step kernel (hh matvec only) ----------------
// 128 blocks x 1024 threads; each hidden unit owned by a warp PAIR (K-split).
// Weight routing per gate: i,f -> L1-pinned (__ldg, 128KB/block);
//                          g   -> SMEM (preloaded once, 64KB, separate port);
//                          o   -> L2 stream (__ldcg).
__global__ void __launch_bounds__(PBLOCK, 1)
lstm_layer_kernel(const unsigned short* __restrict__ Wq,  // layer hh weights (biased u16)
                  const float* __restrict__ scl,          // per-row scales [NG]
                  float* __restrict__ out) {              // [TT][NH] hidden out
    extern __shared__ char smem_dyn[];
    uint4*  smW  = (uint4*)smem_dyn;                       // [UPB*KH4] gate-g weights
    float4* sh4  = (float4*)(smem_dyn + SH4_OFF);          // [512] h_{t-1}
    float*  comb = (float*)(smem_dyn + COMB_OFF);          // [UPB*4] high-half partials

    const int tid  = threadIdx.x;
    const int lane = tid & 31;
    const int widx = tid >> 5;        // 0..31
    const int uw   = widx & 15;       // unit within block
    const int half = widx >> 4;       // K-half
    const int u    = blockIdx.x * UPB + uw;
    const uint4* W = (const uint4*)Wq + (size_t)u * KH4 + half * KH4H;
    const int GS   = NH * KH4;        // uint4 stride between gate blocks
    const int vb   = half * 256;      // float4 base of this half in sh4
    const bool epi = (half == 0) && (lane == 0);   // epilogue lane

    // preload gate-g (gate index 2) weights for this block's 16 units into SMEM
    {
        const uint4* Wg = (const uint4*)Wq + (size_t)2 * NH * KH4;
        for (int i = tid; i < UPB * KH4; i += PBLOCK) {
            int unit = i >> 8;                    // /KH4
            int j    = i & (KH4 - 1);
            smW[i] = __ldcg(Wg + (size_t)(blockIdx.x * UPB + unit) * KH4 + j);
        }
    }
    const uint4* smWme = smW + uw * KH4 + half * KH4H;   // this warp's half-row

    // loop-invariant dequant scales (registers, loaded once)
    const float sc0 = scl[u];
    const float sc1 = scl[NH + u];
    const float sc2 = scl[2 * NH + u];
    const float sc3 = scl[3 * NH + u];

    unsigned sense = 0;
    float c = 0.f;                    // cell state (low warp, lane 0)

    for (int t = 0; t < TT; ++t) {
        // prefetch pre-gate values (depend only on t) -- overlaps the dot loop
        float p0 = 0.f, p1 = 0.f, p2 = 0.f, p3 = 0.f;
        if (epi) {
            const float* pt = g_pre + (size_t)t * NG;
            p0 = __ldcg(pt + u);
            p1 = __ldcg(pt + NH + u);
            p2 = __ldcg(pt + 2 * NH + u);
            p3 = __ldcg(pt + 3 * NH + u);
        }
        if (tid < 512)
            sh4[tid] = (t > 0)
                ? __ldcg((const float4*)out + (size_t)(t - 1) * KF4 + tid)
                : make_float4(0.f, 0.f, 0.f, 0.f);
        __syncthreads();   // also covers the smW preload before first use

        float a0 = 0.f, a1 = 0.f, a2 = 0.f, a3 = 0.f;
        #pragma unroll 2
        for (int j = lane; j < KH4H; j += 32) {
            const float4 lo = sh4[vb + 2 * j], hi = sh4[vb + 2 * j + 1];
            const float vs = lo.x + lo.y + lo.z + lo.w
                           + hi.x + hi.y + hi.z + hi.w;
            uint4 w;
            w = __ldg (W + j);          ACC8RAW(a0, w, lo, hi, vs);   // L1-pinned
            w = __ldg (W + GS + j);     ACC8RAW(a1, w, lo, hi, vs);   // L1-pinned
            w = smWme[j];               ACC8RAW(a2, w, lo, hi, vs);   // SMEM
            w = __ldcg(W + 3 * GS + j); ACC8RAW(a3, w, lo, hi, vs);   // L2 stream
        }
        #pragma unroll
        for (int o = 16; o; o >>= 1) {
            a0 += __shfl_xor_sync(0xffffffffu, a0, o);
            a1 += __shfl_xor_sync(0xffffffffu, a1, o);
            a2 += __shfl_xor_sync(0xffffffffu, a2, o);
            a3 += __shfl_xor_sync(0xffffffffu, a3, o);
        }
        if (half == 1 && lane == 0) {   // high warp publishes; low warp only READS
            comb[uw * 4 + 0] = a0; comb[uw * 4 + 1] = a1;
            comb[uw * 4 + 2] = a2; comb[uw * 4 + 3] = a3;
        }
        __syncthreads();

        if (epi) {
            a0 += comb[uw * 4 + 0]; a1 += comb[uw * 4 + 1];
            a2 += comb[uw * 4 + 2]; a3 += comb[uw * 4 + 3];
            float ig = fmaf(a0, sc0, p0);
            float fg = fmaf(a1, sc1, p1);
            float gg = fmaf(a2, sc2, p2);
            float og = fmaf(a3, sc3, p3);
            c = sigf(fg) * c + sigf(ig) * tanh_fast(gg);
            out[(size_t)t * NH + u] = sigf(og) * tanh_fast(c);
        }

        grid_barrier(sense);   // 256 flips per launch (even parity: replay-safe)
    }
}

// ---------------- epilogue: states[t] = h3[t] @ w_sp^T + b_sp ----------------
__global__ void proj_kernel(const float* __restrict__ wsp, const float* __restrict__ bsp,
                            float* __restrict__ out) {
    __shared__ float4 shh[KF4];
    const int t = blockIdx.x;
    const int tid = threadIdx.x;    // 256 threads
    const float4* h4 = (const float4*)g_hsB + (size_t)t * KF4;  // layer3 output in B
    shh[tid]       = h4[tid];
    shh[tid + 256] = h4[tid + 256];
    __syncthreads();
    const int widx = tid >> 5, lane = tid & 31;
    for (int o = widx; o < 64; o += 8) {
        const float4* wr = (const float4*)wsp + (size_t)o * KF4;
        float s = 0.f;
        #pragma unroll 4
        for (int i = lane; i < KF4; i += 32) {
            float4 w = __ldg(wr + i);
            float4 hv = shh[i];
            s += w.x * hv.x + w.y * hv.y + w.z * hv.z + w.w * hv.w;
        }
        #pragma unroll
        for (int off = 16; off; off >>= 1) s += __shfl_xor_sync(0xffffffffu, s, off);
        if (lane == 0) out[(size_t)t * 64 + o] = s + bsp[o];
    }
}

// ---------------- launch ----------------
extern "C" void kernel_launch(void* const* d_in, const int* in_sizes, int n_in,
                              void* d_out, int out_size) {
    const float* z      = (const float*)d_in[0];
    const float* w_ih0  = (const float*)d_in[1];
    const float* w_hh0  = (const float*)d_in[2];
    const float* b_ih0  = (const float*)d_in[3];
    const float* b_hh0  = (const float*)d_in[4];
    const float* w_ih_r = (const float*)d_in[5];
    const float* w_hh_r = (const float*)d_in[6];
    const float* b_ih_r = (const float*)d_in[7];
    const float* b_hh_r = (const float*)d_in[8];
    const float* w_sp   = (const float*)d_in[9];
    const float* b_sp   = (const float*)d_in[10];
    float* out = (float*)d_out;

    static unsigned short* q_hh_p = nullptr;
    static float* s_hh_p = nullptr;
    static float* bias_p = nullptr;
    static float* hsA_p = nullptr;
    static float* hsB_p = nullptr;
    if (!q_hh_p) {
        cudaGetSymbolAddress((void**)&q_hh_p, q_hh);
        cudaGetSymbolAddress((void**)&s_hh_p, s_hh);
        cudaGetSymbolAddress((void**)&bias_p, g_bias);
        cudaGetSymbolAddress((void**)&hsA_p, g_hsA);
        cudaGetSymbolAddress((void**)&hsB_p, g_hsB);
        cudaFuncSetAttribute(lstm_layer_kernel,
                             cudaFuncAttributeMaxDynamicSharedMemorySize, SMEM_DYN);
        // ~74KB smem; leave the rest as L1 for the pinned i,f gates
        cudaFuncSetAttribute(lstm_layer_kernel,
                             cudaFuncAttributePreferredSharedMemoryCarveout, 34);
    }

    dim3 ggrid(NG / 128, TT / 128);   // 64 x 2 = 128 blocks (one wave)

    bias_kernel<<<64, 512>>>(b_ih0, b_hh0, b_ih_r, b_hh_r);
    quant_kernel<<<448, 512>>>(w_hh0, w_hh_r);
    prefill_kernel<<<TT, 1024>>>();
    pre0_kernel<<<128, 256>>>(w_ih0, z);

    // layer 0 -> hsA
    lstm_layer_kernel<<<GRID, PBLOCK, SMEM_DYN>>>(q_hh_p, s_hh_p, hsA_p);
    // layer 1: pre = hsA @ w_ih_r[0]^T + bias1 ; -> hsB
    gemm_pre_kernel<<<ggrid, 256>>>(hsA_p, w_ih_r, bias_p + 1 * NG);
    lstm_layer_kernel<<<GRID, PBLOCK, SMEM_DYN>>>(q_hh_p + (size_t)1 * NG * NH, s_hh_p + 1 * NG, hsB_p);
    // layer 2
    gemm_pre_kernel<<<ggrid, 256>>>(hsB_p, w_ih_r + (size_t)1 * NG * NH, bias_p + 2 * NG);
    lstm_layer_kernel<<<GRID, PBLOCK, SMEM_DYN>>>(q_hh_p + (size_t)2 * NG * NH, s_hh_p + 2 * NG, hsA_p);
    // layer 3
    gemm_pre_kernel<<<ggrid, 256>>>(hsA_p, w_ih_r + (size_t)2 * NG * NH, bias_p + 3 * NG);
    lstm_layer_kernel<<<GRID, PBLOCK, SMEM_DYN>>>(q_hh_p + (size_t)3 * NG * NH, s_hh_p + 3 * NG, hsB_p);

    proj_kernel<<<TT, 256>>>(w_sp, b_sp, out);
}

// round 11
// speedup vs baseline: 1.1491x; 1.0214x over previous
#include <cuda_runtime.h>
#include <math.h>
#include <stdint.h>

// Problem constants
#define NZ   256
#define NH   2048
#define NG   8192      // 4*NH gate rows
#define TT   256       // timesteps
#define KF4  (NH/4)    // 512 float4 per h-vector
#define PBLOCK 512               // 16 warps: one warp per hidden unit (full row)
#define UPB    16                // hidden units per block
#define GRID   (NH/UPB)          // 128 blocks
#define KH4    256               // uint4 per hh row (2048 weights)
#define BMAGIC 8421376.0f        // 2^23 + 32768 (biased-u16 offset)

// dynamic smem layout: [0,64K) gate-g weights; [64K,72K) sh4
#define SMW_BYTES  (UPB * KH4 * 16)            // 65536
#define SH4_OFF    (SMW_BYTES)                 // 65536
#define SMEM_DYN   (SH4_OFF + 8192)            // 73728 bytes

// ---------------- device scratch (no allocations allowed) ----------------
__device__ float g_bias[4][NG];          // b_ih + b_hh per layer
__device__ float g_pre[TT * NG];         // per-layer precomputed ih gates (+bias), 8.4MB
__device__ float g_hsA[TT * NH];         // ping-pong hidden-sequence buffers
__device__ float g_hsB[TT * NH];
__device__ unsigned g_count;             // grid barrier (returns to 0)
__device__ unsigned g_sense;             // parity; 256 flips/launch (even) -> replay-safe

// quantized hh weights for all 4 layers, biased uint16 (q = round(w/s)+32768)
__device__ unsigned short q_hh[(size_t)4 * NG * NH];   // 134 MB
__device__ float s_hh[4 * NG];           // per-row dequant scales

// HW tanh (max err ~1e-5, well inside budget); sigmoid via exact identity
__device__ __forceinline__ float tanh_fast(float x) {
    float y;
    asm("tanh.approx.f32 %0, %1;" : "=f"(y) : "f"(x));
    return y;
}
__device__ __forceinline__ float sigf(float x) {
    return fmaf(0.5f, tanh_fast(0.5f * x), 0.5f);
}

// biased-u16 -> float WITHOUT bias removal: value = 2^23 + 32768 + q_signed
#define CVR_LO(v) (__uint_as_float(__byte_perm((v), 0x4B000000u, 0x7410)))
#define CVR_HI(v) (__uint_as_float(__byte_perm((v), 0x4B000000u, 0x7632)))

// accumulate one uint4 (8 raw weights) against 8 values (two float4) + bias fold
#define ACC8RAW(acc, w, lo, hi, vs)                   \
    do {                                              \
        acc = fmaf(CVR_LO((w).x), (lo).x, acc);       \
        acc = fmaf(CVR_HI((w).x), (lo).y, acc);       \
        acc = fmaf(CVR_LO((w).y), (lo).z, acc);       \
        acc = fmaf(CVR_HI((w).y), (lo).w, acc);       \
        acc = fmaf(CVR_LO((w).z), (hi).x, acc);       \
        acc = fmaf(CVR_HI((w).z), (hi).y, acc);       \
        acc = fmaf(CVR_LO((w).w), (hi).z, acc);       \
        acc = fmaf(CVR_HI((w).w), (hi).w, acc);       \
        acc = fmaf(-BMAGIC, (vs), acc);               \
    } while (0)

// ---------------- prologue: summed biases ----------------
__global__ void bias_kernel(const float* __restrict__ bi0, const float* __restrict__ bh0,
                            const float* __restrict__ bir, const float* __restrict__ bhr) {
    int idx = blockIdx.x * blockDim.x + threadIdx.x;   // 4*NG threads
    if (idx < 4 * NG) {
        int l = idx >> 13;
        int r = idx & (NG - 1);
        float v = (l == 0) ? (bi0[r] + bh0[r])
                           : (bir[(size_t)(l - 1) * NG + r] + bhr[(size_t)(l - 1) * NG + r]);
        g_bias[l][r] = v;
    }
}

// ---------------- prologue: quantize the 4 hh matrices to biased u16 ----------------
__global__ void quant_kernel(const float* __restrict__ whh0,
                             const float* __restrict__ whhr) {
    int gw   = (blockIdx.x * blockDim.x + threadIdx.x) >> 5;
    int lane = threadIdx.x & 31;
    int nw   = (gridDim.x * blockDim.x) >> 5;
    for (int r = gw; r < 4 * NG; r += nw) {
        int l  = r >> 13;
        int rr = r & (NG - 1);
        const float* src = (l == 0) ? whh0 + (size_t)rr * NH
                                    : whhr + ((size_t)(l - 1) * NG + rr) * NH;
        const float4* s4 = (const float4*)src;
        float m = 0.f;
        #pragma unroll 4
        for (int i = lane; i < KF4; i += 32) {
            float4 v = s4[i];
            m = fmaxf(m, fmaxf(fmaxf(fabsf(v.x), fabsf(v.y)), fmaxf(fabsf(v.z), fabsf(v.w))));
        }
        #pragma unroll
        for (int o = 16; o; o >>= 1) m = fmaxf(m, __shfl_xor_sync(0xffffffffu, m, o));
        float qs = (m > 0.f) ? 32767.0f / m : 0.f;
        if (lane == 0) s_hh[r] = (m > 0.f) ? m / 32767.0f : 0.f;
        ushort4* d4 = (ushort4*)(q_hh + (size_t)r * NH);
        #pragma unroll 4
        for (int i = lane; i < KF4; i += 32) {
            float4 v = s4[i];
            ushort4 o;
            o.x = (unsigned short)(__float2int_rn(v.x * qs) + 32768);
            o.y = (unsigned short)(__float2int_rn(v.y * qs) + 32768);
            o.z = (unsigned short)(__float2int_rn(v.z * qs) + 32768);
            o.w = (unsigned short)(__float2int_rn(v.w * qs) + 32768);
            d4[i] = o;
        }
    }
}

// ---------------- prologue: g_pre[t][r] = bias0[r] for all t (layer0 default) -------
__global__ void prefill_kernel() {
    int t = blockIdx.x;
    for (int r = threadIdx.x; r < NG; r += blockDim.x)
        g_pre[(size_t)t * NG + r] = g_bias[0][r];
}

// ---------------- prologue: overwrite t=0 with z @ W_ih0^T + bias0 ----------------
__global__ void pre0_kernel(const float* __restrict__ wih0, const float* __restrict__ z) {
    int gw   = (blockIdx.x * blockDim.x + threadIdx.x) >> 5;
    int lane = threadIdx.x & 31;
    int nw   = (gridDim.x * blockDim.x) >> 5;
    for (int row = gw; row < NG; row += nw) {
        const float* wr = wih0 + (size_t)row * NZ;
        float s = 0.f;
        for (int k = lane; k < NZ; k += 32) s += wr[k] * z[k];
        #pragma unroll
        for (int o = 16; o; o >>= 1) s += __shfl_xor_sync(0xffffffffu, s, o);
        if (lane == 0) g_pre[row] = s + g_bias[0][row];
    }
}

// ---------------- per-layer ih GEMM: pre[t][row] = X[t]·W[row] + bias[row] ----------
// X: [TT][NH] fp32, W: [NG][NH] fp32. 128x128 tile, BK=16, 256 threads, 8x8 micro.
#define GBK 16
__global__ void __launch_bounds__(256, 1)
gemm_pre_kernel(const float* __restrict__ X,
                const float* __restrict__ Wf,
                const float* __restrict__ bias) {
    __shared__ float Xs[GBK][132];   // [k][t], padded stride
    __shared__ float Ws[GBK][132];   // [k][row]
    const int tid = threadIdx.x;
    const int rb  = blockIdx.x * 128;   // gate-row base
    const int tb  = blockIdx.y * 128;   // t base
    const int tx  = tid & 15, ty = tid >> 4;

    float acc[8][8];
    #pragma unroll
    for (int i = 0; i < 8; ++i)
        #pragma unroll
        for (int j = 0; j < 8; ++j) acc[i][j] = 0.f;

    float4 px[2], pw[2];
    // prefetch first K-tile (coalesced: 4 consecutive threads cover one row's 64B)
    #pragma unroll
    for (int r = 0; r < 2; ++r) {
        int idx = tid + r * 256;            // 0..511
        int tt  = idx >> 2;                 // row/t index 0..127
        int k4  = idx & 3;                  // 0..3 (float4 within 16-wide K tile)
        px[r] = *(const float4*)(X  + (size_t)(tb + tt) * NH + k4 * 4);
        pw[r] = *(const float4*)(Wf + (size_t)(rb + tt) * NH + k4 * 4);
    }

    for (int kk = 0; kk < NH; kk += GBK) {
        __syncthreads();   // previous tile's compute done
        #pragma unroll
        for (int r = 0; r < 2; ++r) {
            int idx = tid + r * 256;
            int tt  = idx >> 2;
            int k0  = (idx & 3) * 4;
            Xs[k0 + 0][tt] = px[r].x; Xs[k0 + 1][tt] = px[r].y;
            Xs[k0 + 2][tt] = px[r].z; Xs[k0 + 3][tt] = px[r].w;
            Ws[k0 + 0][tt] = pw[r].x; Ws[k0 + 1][tt] = pw[r].y;
            Ws[k0 + 2][tt] = pw[r].z; Ws[k0 + 3][tt] = pw[r].w;
        }
        __syncthreads();
        if (kk + GBK < NH) {    // prefetch next tile (overlaps compute)
            #pragma unroll
            for (int r = 0; r < 2; ++r) {
                int idx = tid + r * 256;
                int tt  = idx >> 2;
                int k4  = idx & 3;
                px[r] = *(const float4*)(X  + (size_t)(tb + tt) * NH + kk + GBK + k4 * 4);
                pw[r] = *(const float4*)(Wf + (size_t)(rb + tt) * NH + kk + GBK + k4 * 4);
            }
        }
        #pragma unroll
        for (int k = 0; k < GBK; ++k) {
            float4 x0 = *(const float4*)&Xs[k][ty * 8];
            float4 x1 = *(const float4*)&Xs[k][ty * 8 + 4];
            float4 w0 = *(const float4*)&Ws[k][tx * 8];
            float4 w1 = *(const float4*)&Ws[k][tx * 8 + 4];
            float xr[8] = {x0.x, x0.y, x0.z, x0.w, x1.x, x1.y, x1.z, x1.w};
            float wr[8] = {w0.x, w0.y, w0.z, w0.w, w1.x, w1.y, w1.z, w1.w};
            #pragma unroll
            for (int i = 0; i < 8; ++i)
                #pragma unroll
                for (int j = 0; j < 8; ++j)
                    acc[i][j] = fmaf(xr[i], wr[j], acc[i][j]);
        }
    }

    const float4 b0 = *(const float4*)&bias[rb + tx * 8];
    const float4 b1 = *(const float4*)&bias[rb + tx * 8 + 4];
    #pragma unroll
    for (int i = 0; i < 8; ++i) {
        float* cp = g_pre + (size_t)(tb + ty * 8 + i) * NG + rb + tx * 8;
        float4 v0 = make_float4(acc[i][0] + b0.x, acc[i][1] + b0.y,
                                acc[i][2] + b0.z, acc[i][3] + b0.w);
        float4 v1 = make_float4(acc[i][4] + b1.x, acc[i][5] + b1.y,
                                acc[i][6] + b1.z, acc[i][7] + b1.w);
        *(float4*)cp       = v0;
        *(float4*)(cp + 4) = v1;
    }
}

// ---------------- R8 grid barrier: single atomic arrival + relaxed spin -------------
// atom.release orders this block's prior stores; spin is ld.relaxed (L2 read,
// no L1 invalidate). Cross-block h data is read via __ldcg, so L1 holds only
// read-only weights, which legally persist across the barrier.
__device__ __forceinline__ void grid_barrier(unsigned& sense) {
    __syncthreads();
    if (threadIdx.x == 0) {
        unsigned s = sense ^ 1u;
        sense = s;
        unsigned old;
        asm volatile("atom.release.gpu.global.add.u32 %0, [%1], %2;"
                     : "=r"(old) : "l"(&g_count), "r"(1u) : "memory");
        if (old == (unsigned)(GRID - 1)) {
            asm volatile("st.relaxed.gpu.global.u32 [%0], %1;"
                         :: "l"(&g_count), "r"(0u) : "memory");
            asm volatile("st.release.gpu.global.u32 [%0], %1;"
                         :: "l"(&g_sense), "r"(s) : "memory");
        } else {
            unsigned v;
            do {
                asm volatile("ld.relaxed.gpu.global.u32 %0, [%1];"
                             : "=r"(v) : "l"(&g_sense) : "memory");
            } while (v != s);
        }
    }
    __syncthreads();
}

// ---------------- per-layer persistent step kernel (hh matvec only) ----------------
// 128 blocks x 512 threads; ONE WARP OWNS ONE FULL HIDDEN UNIT (no K-split).
// 512 threads -> 128 regs/thread: deep unroll + load batching hides LDS/L2 latency.
// Weight routing per gate: i,f -> L1-pinned (__ldg, 128KB/block);
//                          g   -> SMEM (preloaded once, 64KB, separate port);
//                          o   -> L2 stream (__ldcg).
__global__ void __launch_bounds__(PBLOCK, 1)
lstm_layer_kernel(const unsigned short* __restrict__ Wq,  // layer hh weights (biased u16)
                  const float* __restrict__ scl,          // per-row scales [NG]
                  float* __restrict__ out) {              // [TT][NH] hidden out
    extern __shared__ char smem_dyn[];
    uint4*  smW = (uint4*)smem_dyn;                       // [UPB*KH4] gate-g weights
    float4* sh4 = (float4*)(smem_dyn + SH4_OFF);          // [512] h_{t-1}

    const int tid  = threadIdx.x;
    const int lane = tid & 31;
    const int widx = tid >> 5;        // 0..15 = unit within block
    const int u    = blockIdx.x * UPB + widx;
    const int GS   = NH * KH4;        // uint4 stride between gate blocks
    const uint4* W = (const uint4*)Wq + (size_t)u * KH4;

    // preload gate-g (gate index 2) weights for this block's 16 units into SMEM
    {
        const uint4* Wg = (const uint4*)Wq + (size_t)2 * GS;
        for (int i = tid; i < UPB * KH4; i += PBLOCK) {
            int unit = i >> 8;                    // /KH4
            int j    = i & (KH4 - 1);
            smW[i] = __ldcg(Wg + (size_t)(blockIdx.x * UPB + unit) * KH4 + j);
        }
    }
    const uint4* smWme = smW + widx * KH4;   // this warp's gate-g row

    // loop-invariant dequant scales (registers, loaded once)
    const float sc0 = scl[u];
    const float sc1 = scl[NH + u];
    const float sc2 = scl[2 * NH + u];
    const float sc3 = scl[3 * NH + u];

    unsigned sense = 0;
    float c = 0.f;                    // cell state (lane 0)

    for (int t = 0; t < TT; ++t) {
        // prefetch pre-gate values (depend only on t) -- overlaps the dot loop
        float p0 = 0.f, p1 = 0.f, p2 = 0.f, p3 = 0.f;
        if (lane == 0) {
            const float* pt = g_pre + (size_t)t * NG;
            p0 = __ldcg(pt + u);
            p1 = __ldcg(pt + NH + u);
            p2 = __ldcg(pt + 2 * NH + u);
            p3 = __ldcg(pt + 3 * NH + u);
        }
        // stage h_{t-1}: 512 threads -> one float4 each
        sh4[tid] = (t > 0)
            ? __ldcg((const float4*)out + (size_t)(t - 1) * KF4 + tid)
            : make_float4(0.f, 0.f, 0.f, 0.f);
        __syncthreads();   // also covers the smW preload before first use

        float a0 = 0.f, a1 = 0.f, a2 = 0.f, a3 = 0.f;
        #pragma unroll 4
        for (int j = lane; j < KH4; j += 32) {
            const float4 lo = sh4[2 * j], hi = sh4[2 * j + 1];
            const float vs = lo.x + lo.y + lo.z + lo.w
                           + hi.x + hi.y + hi.z + hi.w;
            uint4 w;
            w = __ldg (W + j);          ACC8RAW(a0, w, lo, hi, vs);   // L1-pinned
            w = __ldg (W + GS + j);     ACC8RAW(a1, w, lo, hi, vs);   // L1-pinned
            w = smWme[j];               ACC8RAW(a2, w, lo, hi, vs);   // SMEM
            w = __ldcg(W + 3 * GS + j); ACC8RAW(a3, w, lo, hi, vs);   // L2 stream
        }
        #pragma unroll
        for (int o = 16; o; o >>= 1) {
            a0 += __shfl_xor_sync(0xffffffffu, a0, o);
            a1 += __shfl_xor_sync(0xffffffffu, a1, o);
            a2 += __shfl_xor_sync(0xffffffffu, a2, o);
            a3 += __shfl_xor_sync(0xffffffffu, a3, o);
        }

        if (lane == 0) {
            float ig = fmaf(a0, sc0, p0);
            float fg = fmaf(a1, sc1, p1);
            float gg = fmaf(a2, sc2, p2);
            float og = fmaf(a3, sc3, p3);
            c = sigf(fg) * c + sigf(ig) * tanh_fast(gg);
            out[(size_t)t * NH + u] = sigf(og) * tanh_fast(c);
        }

        grid_barrier(sense);   // 256 flips per launch (even parity: replay-safe)
    }
}

// ---------------- epilogue: states[t] = h3[t] @ w_sp^T + b_sp ----------------
__global__ void proj_kernel(const float* __restrict__ wsp, const float* __restrict__ bsp,
                            float* __restrict__ out) {
    __shared__ float4 shh[KF4];
    const int t = blockIdx.x;
    const int tid = threadIdx.x;    // 256 threads
    const float4* h4 = (const float4*)g_hsB + (size_t)t * KF4;  // layer3 output in B
    shh[tid]       = h4[tid];
    shh[tid + 256] = h4[tid + 256];
    __syncthreads();
    const int widx = tid >> 5, lane = tid & 31;
    for (int o = widx; o < 64; o += 8) {
        const float4* wr = (const float4*)wsp + (size_t)o * KF4;
        float s = 0.f;
        #pragma unroll 4
        for (int i = lane; i < KF4; i += 32) {
            float4 w = __ldg(wr + i);
            float4 hv = shh[i];
            s += w.x * hv.x + w.y * hv.y + w.z * hv.z + w.w * hv.w;
        }
        #pragma unroll
        for (int off = 16; off; off >>= 1) s += __shfl_xor_sync(0xffffffffu, s, off);
        if (lane == 0) out[(size_t)t * 64 + o] = s + bsp[o];
    }
}

// ---------------- launch ----------------
extern "C" void kernel_launch(void* const* d_in, const int* in_sizes, int n_in,
                              void* d_out, int out_size) {
    const float* z      = (const float*)d_in[0];
    const float* w_ih0  = (const float*)d_in[1];
    const float* w_hh0  = (const float*)d_in[2];
    const float* b_ih0  = (const float*)d_in[3];
    const float* b_hh0  = (const float*)d_in[4];
    const float* w_ih_r = (const float*)d_in[5];
    const float* w_hh_r = (const float*)d_in[6];
    const float* b_ih_r = (const float*)d_in[7];
    const float* b_hh_r = (const float*)d_in[8];
    const float* w_sp   = (const float*)d_in[9];
    const float* b_sp   = (const float*)d_in[10];
    float* out = (float*)d_out;

    static unsigned short* q_hh_p = nullptr;
    static float* s_hh_p = nullptr;
    static float* bias_p = nullptr;
    static float* hsA_p = nullptr;
    static float* hsB_p = nullptr;
    if (!q_hh_p) {
        cudaGetSymbolAddress((void**)&q_hh_p, q_hh);
        cudaGetSymbolAddress((void**)&s_hh_p, s_hh);
        cudaGetSymbolAddress((void**)&bias_p, g_bias);
        cudaGetSymbolAddress((void**)&hsA_p, g_hsA);
        cudaGetSymbolAddress((void**)&hsB_p, g_hsB);
        cudaFuncSetAttribute(lstm_layer_kernel,
                             cudaFuncAttributeMaxDynamicSharedMemorySize, SMEM_DYN);
        // ~72KB smem; leave the rest as L1 for the pinned i,f gates
        cudaFuncSetAttribute(lstm_layer_kernel,
                             cudaFuncAttributePreferredSharedMemoryCarveout, 34);
    }

    dim3 ggrid(NG / 128, TT / 128);   // 64 x 2 = 128 blocks (one wave)

    bias_kernel<<<64, 512>>>(b_ih0, b_hh0, b_ih_r, b_hh_r);
    quant_kernel<<<448, 512>>>(w_hh0, w_hh_r);
    prefill_kernel<<<TT, 1024>>>();
    pre0_kernel<<<128, 256>>>(w_ih0, z);

    // layer 0 -> hsA
    lstm_layer_kernel<<<GRID, PBLOCK, SMEM_DYN>>>(q_hh_p, s_hh_p, hsA_p);
    // layer 1: pre = hsA @ w_ih_r[0]^T + bias1 ; -> hsB
    gemm_pre_kernel<<<ggrid, 256>>>(hsA_p, w_ih_r, bias_p + 1 * NG);
    lstm_layer_kernel<<<GRID, PBLOCK, SMEM_DYN>>>(q_hh_p + (size_t)1 * NG * NH, s_hh_p + 1 * NG, hsB_p);
    // layer 2
    gemm_pre_kernel<<<ggrid, 256>>>(hsB_p, w_ih_r + (size_t)1 * NG * NH, bias_p + 2 * NG);
    lstm_layer_kernel<<<GRID, PBLOCK, SMEM_DYN>>>(q_hh_p + (size_t)2 * NG * NH, s_hh_p + 2 * NG, hsA_p);
    // layer 3
    gemm_pre_kernel<<<ggrid, 256>>>(hsA_p, w_ih_r + (size_t)2 * NG * NH, bias_p + 3 * NG);
    lstm_layer_kernel<<<GRID, PBLOCK, SMEM_DYN>>>(q_hh_p + (size_t)3 * NG * NH, s_hh_p + 3 * NG, hsB_p);

    proj_kernel<<<TT, 256>>>(w_sp, b_sp, out);
}

// round 12
// speedup vs baseline: 1.3709x; 1.1930x over previous
#include <cuda_runtime.h>
#include <math.h>
#include <stdint.h>

// Problem constants
#define NZ   256
#define NH   2048
#define NG   8192      // 4*NH gate rows
#define TT   256       // timesteps
#define KF4  (NH/4)    // 512 float4 per h-vector
#define PBLOCK 512               // 16 warps: one warp per hidden unit (full row)
#define UPB    16                // hidden units per block
#define GRID   (NH/UPB)          // 128 blocks
#define KQ4    256               // uint4 per q8 row (4096 bytes: 2048 hi + 2048 lo)
#define GSQ    (NH * KQ4)        // uint4 stride between gate blocks

// dynamic smem: [0,64K) gate-g q8 weights; [64K,68K) h int8 (512 hi + 512 lo int32)
#define SMW_BYTES  (UPB * KQ4 * 16)            // 65536
#define SMH_OFF    (SMW_BYTES)
#define SMEM_DYN   (SMH_OFF + 4096)            // 69632 bytes

// ---------------- device scratch (no allocations allowed) ----------------
__device__ float g_bias[4][NG];          // b_ih + b_hh per layer
__device__ float g_pre[TT * NG];         // per-layer precomputed ih gates (+bias), 8.4MB
__device__ float g_hsA[TT * NH];         // ping-pong hidden-sequence buffers (fp32, GEMM food)
__device__ float g_hsB[TT * NH];
__device__ unsigned g_count;             // grid barrier (returns to 0)
__device__ unsigned g_sense;             // parity; 256 flips/launch (even) -> replay-safe
__device__ unsigned short g_hq8[2][NH];  // packed h int8 (q1 | q2<<8), parity double-buffer

// dual-int8 hh weights, all 4 layers. Row layout (4096B): bytes[0,2048)=q1 planes
// packed 4/int32, bytes[2048,4096)=q2. W = (m/127)*(q1 + q2/254), per-row max m.
__device__ unsigned char q8_hh[(size_t)4 * NG * 4096];   // 134 MB
__device__ float s_hh[4 * NG];           // per-row raw max m

// HW tanh (max err ~1e-5); sigmoid via exact identity
__device__ __forceinline__ float tanh_fast(float x) {
    float y;
    asm("tanh.approx.f32 %0, %1;" : "=f"(y) : "f"(x));
    return y;
}
__device__ __forceinline__ float sigf(float x) {
    return fmaf(0.5f, tanh_fast(0.5f * x), 0.5f);
}

// 12 dp4a: hi*hi -> ah ; hi*lo + lo*hi -> am  (lo*lo dropped, rel ~6e-5)
#define DP4ACC(ah, am, whi, wlo, hh, hl)                       \
    do {                                                       \
        ah = __dp4a((int)(whi).x, (int)(hh).x, ah);            \
        ah = __dp4a((int)(whi).y, (int)(hh).y, ah);            \
        ah = __dp4a((int)(whi).z, (int)(hh).z, ah);            \
        ah = __dp4a((int)(whi).w, (int)(hh).w, ah);            \
        am = __dp4a((int)(whi).x, (int)(hl).x, am);            \
        am = __dp4a((int)(whi).y, (int)(hl).y, am);            \
        am = __dp4a((int)(whi).z, (int)(hl).z, am);            \
        am = __dp4a((int)(whi).w, (int)(hl).w, am);            \
        am = __dp4a((int)(wlo).x, (int)(hh).x, am);            \
        am = __dp4a((int)(wlo).y, (int)(hh).y, am);            \
        am = __dp4a((int)(wlo).z, (int)(hh).z, am);            \
        am = __dp4a((int)(wlo).w, (int)(hh).w, am);            \
    } while (0)

// ---------------- prologue: summed biases ----------------
__global__ void bias_kernel(const float* __restrict__ bi0, const float* __restrict__ bh0,
                            const float* __restrict__ bir, const float* __restrict__ bhr) {
    int idx = blockIdx.x * blockDim.x + threadIdx.x;   // 4*NG threads
    if (idx < 4 * NG) {
        int l = idx >> 13;
        int r = idx & (NG - 1);
        float v = (l == 0) ? (bi0[r] + bh0[r])
                           : (bir[(size_t)(l - 1) * NG + r] + bhr[(size_t)(l - 1) * NG + r]);
        g_bias[l][r] = v;
    }
}

// ---------------- prologue: quantize the 4 hh matrices to dual-int8 ----------------
__global__ void quant_kernel(const float* __restrict__ whh0,
                             const float* __restrict__ whhr) {
    int gw   = (blockIdx.x * blockDim.x + threadIdx.x) >> 5;
    int lane = threadIdx.x & 31;
    int nw   = (gridDim.x * blockDim.x) >> 5;
    for (int r = gw; r < 4 * NG; r += nw) {
        int l  = r >> 13;
        int rr = r & (NG - 1);
        const float* src = (l == 0) ? whh0 + (size_t)rr * NH
                                    : whhr + ((size_t)(l - 1) * NG + rr) * NH;
        const float4* s4 = (const float4*)src;
        float m = 0.f;
        #pragma unroll 4
        for (int i = lane; i < KF4; i += 32) {
            float4 v = s4[i];
            m = fmaxf(m, fmaxf(fmaxf(fabsf(v.x), fabsf(v.y)), fmaxf(fabsf(v.z), fabsf(v.w))));
        }
        #pragma unroll
        for (int o = 16; o; o >>= 1) m = fmaxf(m, __shfl_xor_sync(0xffffffffu, m, o));
        float qs = (m > 0.f) ? 127.0f / m : 0.f;
        if (lane == 0) s_hh[r] = m;            // raw max; scale folded in epilogue
        int* d32 = (int*)(q8_hh + (size_t)r * 4096);
        #pragma unroll 4
        for (int i = lane; i < KF4; i += 32) {   // one int32 = 4 weights
            float4 v = s4[i];
            float x0 = v.x * qs, x1 = v.y * qs, x2 = v.z * qs, x3 = v.w * qs;
            int a0 = __float2int_rn(x0), a1 = __float2int_rn(x1);
            int a2 = __float2int_rn(x2), a3 = __float2int_rn(x3);
            int b0 = __float2int_rn((x0 - (float)a0) * 254.f);
            int b1 = __float2int_rn((x1 - (float)a1) * 254.f);
            int b2 = __float2int_rn((x2 - (float)a2) * 254.f);
            int b3 = __float2int_rn((x3 - (float)a3) * 254.f);
            d32[i]       = (a0 & 0xff) | ((a1 & 0xff) << 8) | ((a2 & 0xff) << 16) | ((a3 & 0xff) << 24);
            d32[512 + i] = (b0 & 0xff) | ((b1 & 0xff) << 8) | ((b2 & 0xff) << 16) | ((b3 & 0xff) << 24);
        }
    }
}

// ---------------- prologue: g_pre[t][r] = bias0[r] for all t (layer0 default) -------
__global__ void prefill_kernel() {
    int t = blockIdx.x;
    for (int r = threadIdx.x; r < NG; r += blockDim.x)
        g_pre[(size_t)t * NG + r] = g_bias[0][r];
}

// ---------------- prologue: overwrite t=0 with z @ W_ih0^T + bias0 ----------------
__global__ void pre0_kernel(const float* __restrict__ wih0, const float* __restrict__ z) {
    int gw   = (blockIdx.x * blockDim.x + threadIdx.x) >> 5;
    int lane = threadIdx.x & 31;
    int nw   = (gridDim.x * blockDim.x) >> 5;
    for (int row = gw; row < NG; row += nw) {
        const float* wr = wih0 + (size_t)row * NZ;
        float s = 0.f;
        for (int k = lane; k < NZ; k += 32) s += wr[k] * z[k];
        #pragma unroll
        for (int o = 16; o; o >>= 1) s += __shfl_xor_sync(0xffffffffu, s, o);
        if (lane == 0) g_pre[row] = s + g_bias[0][row];
    }
}

// ---------------- per-layer ih GEMM: pre[t][row] = X[t]·W[row] + bias[row] ----------
#define GBK 16
__global__ void __launch_bounds__(256, 1)
gemm_pre_kernel(const float* __restrict__ X,
                const float* __restrict__ Wf,
                const float* __restrict__ bias) {
    __shared__ float Xs[GBK][132];
    __shared__ float Ws[GBK][132];
    const int tid = threadIdx.x;
    const int rb  = blockIdx.x * 128;
    const int tb  = blockIdx.y * 128;
    const int tx  = tid & 15, ty = tid >> 4;

    float acc[8][8];
    #pragma unroll
    for (int i = 0; i < 8; ++i)
        #pragma unroll
        for (int j = 0; j < 8; ++j) acc[i][j] = 0.f;

    float4 px[2], pw[2];
    #pragma unroll
    for (int r = 0; r < 2; ++r) {
        int idx = tid + r * 256;
        int tt  = idx >> 2;
        int k4  = idx & 3;
        px[r] = *(const float4*)(X  + (size_t)(tb + tt) * NH + k4 * 4);
        pw[r] = *(const float4*)(Wf + (size_t)(rb + tt) * NH + k4 * 4);
    }

    for (int kk = 0; kk < NH; kk += GBK) {
        __syncthreads();
        #pragma unroll
        for (int r = 0; r < 2; ++r) {
            int idx = tid + r * 256;
            int tt  = idx >> 2;
            int k0  = (idx & 3) * 4;
            Xs[k0 + 0][tt] = px[r].x; Xs[k0 + 1][tt] = px[r].y;
            Xs[k0 + 2][tt] = px[r].z; Xs[k0 + 3][tt] = px[r].w;
            Ws[k0 + 0][tt] = pw[r].x; Ws[k0 + 1][tt] = pw[r].y;
            Ws[k0 + 2][tt] = pw[r].z; Ws[k0 + 3][tt] = pw[r].w;
        }
        __syncthreads();
        if (kk + GBK < NH) {
            #pragma unroll
            for (int r = 0; r < 2; ++r) {
                int idx = tid + r * 256;
                int tt  = idx >> 2;
                int k4  = idx & 3;
                px[r] = *(const float4*)(X  + (size_t)(tb + tt) * NH + kk + GBK + k4 * 4);
                pw[r] = *(const float4*)(Wf + (size_t)(rb + tt) * NH + kk + GBK + k4 * 4);
            }
        }
        #pragma unroll
        for (int k = 0; k < GBK; ++k) {
            float4 x0 = *(const float4*)&Xs[k][ty * 8];
            float4 x1 = *(const float4*)&Xs[k][ty * 8 + 4];
            float4 w0 = *(const float4*)&Ws[k][tx * 8];
            float4 w1 = *(const float4*)&Ws[k][tx * 8 + 4];
            float xr[8] = {x0.x, x0.y, x0.z, x0.w, x1.x, x1.y, x1.z, x1.w};
            float wr[8] = {w0.x, w0.y, w0.z, w0.w, w1.x, w1.y, w1.z, w1.w};
            #pragma unroll
            for (int i = 0; i < 8; ++i)
                #pragma unroll
                for (int j = 0; j < 8; ++j)
                    acc[i][j] = fmaf(xr[i], wr[j], acc[i][j]);
        }
    }

    const float4 b0 = *(const float4*)&bias[rb + tx * 8];
    const float4 b1 = *(const float4*)&bias[rb + tx * 8 + 4];
    #pragma unroll
    for (int i = 0; i < 8; ++i) {
        float* cp = g_pre + (size_t)(tb + ty * 8 + i) * NG + rb + tx * 8;
        float4 v0 = make_float4(acc[i][0] + b0.x, acc[i][1] + b0.y,
                                acc[i][2] + b0.z, acc[i][3] + b0.w);
        float4 v1 = make_float4(acc[i][4] + b1.x, acc[i][5] + b1.y,
                                acc[i][6] + b1.z, acc[i][7] + b1.w);
        *(float4*)cp       = v0;
        *(float4*)(cp + 4) = v1;
    }
}

// ---------------- R8 grid barrier: single atomic arrival + relaxed spin -------------
__device__ __forceinline__ void grid_barrier(unsigned& sense) {
    __syncthreads();
    if (threadIdx.x == 0) {
        unsigned s = sense ^ 1u;
        sense = s;
        unsigned old;
        asm volatile("atom.release.gpu.global.add.u32 %0, [%1], %2;"
                     : "=r"(old) : "l"(&g_count), "r"(1u) : "memory");
        if (old == (unsigned)(GRID - 1)) {
            asm volatile("st.relaxed.gpu.global.u32 [%0], %1;"
                         :: "l"(&g_count), "r"(0u) : "memory");
            asm volatile("st.release.gpu.global.u32 [%0], %1;"
                         :: "l"(&g_sense), "r"(s) : "memory");
        } else {
            unsigned v;
            do {
                asm volatile("ld.relaxed.gpu.global.u32 %0, [%1];"
                             : "=r"(v) : "l"(&g_sense) : "memory");
            } while (v != s);
        }
    }
    __syncthreads();
}

// ---------------- per-layer persistent step kernel (dual-int8 dp4a) ----------------
// 128 blocks x 512 threads; one warp = one full hidden unit.
// Gate routing: i,f -> L1-pinned (__ldg, 128KB/block); g -> SMEM; o -> L2 (__ldcg).
// h carried between steps as packed int8 pairs in g_hq8 (parity double-buffered).
__global__ void __launch_bounds__(PBLOCK, 1)
lstm_layer_kernel(const unsigned char* __restrict__ Wq,  // layer q8 base
                  const float* __restrict__ scl,         // per-row raw max [NG]
                  float* __restrict__ out) {             // [TT][NH] fp32 hidden out
    extern __shared__ char smem_dyn[];
    uint4* smW    = (uint4*)smem_dyn;                    // [UPB*KQ4] gate-g weights
    int*   smh_hi = (int*)(smem_dyn + SMH_OFF);          // [512] packed q1 of h
    int*   smh_lo = smh_hi + 512;                        // [512] packed q2 of h

    const int tid  = threadIdx.x;
    const int lane = tid & 31;
    const int widx = tid >> 5;        // 0..15 = unit within block
    const int u    = blockIdx.x * UPB + widx;
    const uint4* W = (const uint4*)Wq + (size_t)u * KQ4;

    // preload gate-g (index 2) q8 rows for this block's 16 units into SMEM
    {
        const uint4* Wg = (const uint4*)Wq + (size_t)2 * GSQ;
        for (int i = tid; i < UPB * KQ4; i += PBLOCK) {
            int unit = i >> 8;                  // /KQ4
            int j    = i & (KQ4 - 1);
            smW[i] = __ldcg(Wg + (size_t)(blockIdx.x * UPB + unit) * KQ4 + j);
        }
    }
    const uint4* smWme = smW + widx * KQ4;

    // dequant scales folded with 1/127^2 (W plane) ; h scale 1/127 folded too
    const float fold = 1.f / 16129.f;          // 1/(127*127)
    const float sc0 = scl[u]          * fold;
    const float sc1 = scl[NH + u]     * fold;
    const float sc2 = scl[2 * NH + u] * fold;
    const float sc3 = scl[3 * NH + u] * fold;

    unsigned sense = 0;
    float c = 0.f;                    // cell state (lane 0)

    for (int t = 0; t < TT; ++t) {
        float p0 = 0.f, p1 = 0.f, p2 = 0.f, p3 = 0.f;
        if (lane == 0) {
            const float* pt = g_pre + (size_t)t * NG;
            p0 = __ldcg(pt + u);
            p1 = __ldcg(pt + NH + u);
            p2 = __ldcg(pt + 2 * NH + u);
            p3 = __ldcg(pt + 3 * NH + u);
        }
        // stage h_{t-1} int8: 512 threads, one int2 (4 packed shorts) each
        if (t > 0) {
            const int2* src = (const int2*)g_hq8[(t - 1) & 1];
            int2 v = __ldcg(src + tid);
            smh_hi[tid] = __byte_perm(v.x, v.y, 0x6420);   // q1 bytes
            smh_lo[tid] = __byte_perm(v.x, v.y, 0x7531);   // q2 bytes
        } else {
            smh_hi[tid] = 0;
            smh_lo[tid] = 0;
        }
        __syncthreads();   // also covers smW preload before first use

        int ah0 = 0, am0 = 0, ah1 = 0, am1 = 0;
        int ah2 = 0, am2 = 0, ah3 = 0, am3 = 0;
        const uint4* Hhi4 = (const uint4*)smh_hi;
        const uint4* Hlo4 = (const uint4*)smh_lo;
        #pragma unroll
        for (int it = 0; it < 4; ++it) {
            const int j = lane + it * 32;        // 0..127
            const uint4 hh = Hhi4[j];
            const uint4 hl = Hlo4[j];
            uint4 w, x;
            w = __ldg (W + j);             x = __ldg (W + 128 + j);             // gate i (L1)
            DP4ACC(ah0, am0, w, x, hh, hl);
            w = __ldg (W + GSQ + j);       x = __ldg (W + GSQ + 128 + j);       // gate f (L1)
            DP4ACC(ah1, am1, w, x, hh, hl);
            w = smWme[j];                  x = smWme[128 + j];                  // gate g (SMEM)
            DP4ACC(ah2, am2, w, x, hh, hl);
            w = __ldcg(W + 3 * GSQ + j);   x = __ldcg(W + 3 * GSQ + 128 + j);   // gate o (L2)
            DP4ACC(ah3, am3, w, x, hh, hl);
        }

        float d0 = fmaf((float)am0, 1.f / 254.f, (float)ah0);
        float d1 = fmaf((float)am1, 1.f / 254.f, (float)ah1);
        float d2 = fmaf((float)am2, 1.f / 254.f, (float)ah2);
        float d3 = fmaf((float)am3, 1.f / 254.f, (float)ah3);
        #pragma unroll
        for (int o = 16; o; o >>= 1) {
            d0 += __shfl_xor_sync(0xffffffffu, d0, o);
            d1 += __shfl_xor_sync(0xffffffffu, d1, o);
            d2 += __shfl_xor_sync(0xffffffffu, d2, o);
            d3 += __shfl_xor_sync(0xffffffffu, d3, o);
        }

        if (lane == 0) {
            float ig = fmaf(d0, sc0, p0);
            float fg = fmaf(d1, sc1, p1);
            float gg = fmaf(d2, sc2, p2);
            float og = fmaf(d3, sc3, p3);
            c = sigf(fg) * c + sigf(ig) * tanh_fast(gg);
            float h = sigf(og) * tanh_fast(c);
            out[(size_t)t * NH + u] = h;
            // quantize h for the next step: h in (-1,1) -> q1 + q2/254 over /127
            float x = h * 127.f;
            int q1 = __float2int_rn(x);
            int q2 = __float2int_rn((x - (float)q1) * 254.f);
            unsigned short pk = (unsigned short)((q1 & 0xff) | ((q2 & 0xff) << 8));
            unsigned short* hp = &g_hq8[t & 1][u];
            asm volatile("st.global.cg.u16 [%0], %1;" :: "l"(hp), "h"(pk) : "memory");
        }

        grid_barrier(sense);   // 256 flips per launch (even parity: replay-safe)
    }
}

// ---------------- epilogue: states[t] = h3[t] @ w_sp^T + b_sp ----------------
__global__ void proj_kernel(const float* __restrict__ wsp, const float* __restrict__ bsp,
                            float* __restrict__ out) {
    __shared__ float4 shh[KF4];
    const int t = blockIdx.x;
    const int tid = threadIdx.x;    // 256 threads
    const float4* h4 = (const float4*)g_hsB + (size_t)t * KF4;  // layer3 output in B
    shh[tid]       = h4[tid];
    shh[tid + 256] = h4[tid + 256];
    __syncthreads();
    const int widx = tid >> 5, lane = tid & 31;
    for (int o = widx; o < 64; o += 8) {
        const float4* wr = (const float4*)wsp + (size_t)o * KF4;
        float s = 0.f;
        #pragma unroll 4
        for (int i = lane; i < KF4; i += 32) {
            float4 w = __ldg(wr + i);
            float4 hv = shh[i];
            s += w.x * hv.x + w.y * hv.y + w.z * hv.z + w.w * hv.w;
        }
        #pragma unroll
        for (int off = 16; off; off >>= 1) s += __shfl_xor_sync(0xffffffffu, s, off);
        if (lane == 0) out[(size_t)t * 64 + o] = s + bsp[o];
    }
}

// ---------------- launch ----------------
extern "C" void kernel_launch(void* const* d_in, const int* in_sizes, int n_in,
                              void* d_out, int out_size) {
    const float* z      = (const float*)d_in[0];
    const float* w_ih0  = (const float*)d_in[1];
    const float* w_hh0  = (const float*)d_in[2];
    const float* b_ih0  = (const float*)d_in[3];
    const float* b_hh0  = (const float*)d_in[4];
    const float* w_ih_r = (const float*)d_in[5];
    const float* w_hh_r = (const float*)d_in[6];
    const float* b_ih_r = (const float*)d_in[7];
    const float* b_hh_r = (const float*)d_in[8];
    const float* w_sp   = (const float*)d_in[9];
    const float* b_sp   = (const float*)d_in[10];
    float* out = (float*)d_out;

    static unsigned char* q8_p = nullptr;
    static float* s_hh_p = nullptr;
    static float* bias_p = nullptr;
    static float* hsA_p = nullptr;
    static float* hsB_p = nullptr;
    if (!q8_p) {
        cudaGetSymbolAddress((void**)&q8_p, q8_hh);
        cudaGetSymbolAddress((void**)&s_hh_p, s_hh);
        cudaGetSymbolAddress((void**)&bias_p, g_bias);
        cudaGetSymbolAddress((void**)&hsA_p, g_hsA);
        cudaGetSymbolAddress((void**)&hsB_p, g_hsB);
        cudaFuncSetAttribute(lstm_layer_kernel,
                             cudaFuncAttributeMaxDynamicSharedMemorySize, SMEM_DYN);
        // ~68KB smem; leave the rest as L1 for the pinned i,f gates (128KB)
        cudaFuncSetAttribute(lstm_layer_kernel,
                             cudaFuncAttributePreferredSharedMemoryCarveout, 32);
    }

    dim3 ggrid(NG / 128, TT / 128);   // 64 x 2 = 128 blocks (one wave)

    bias_kernel<<<64, 512>>>(b_ih0, b_hh0, b_ih_r, b_hh_r);
    quant_kernel<<<448, 512>>>(w_hh0, w_hh_r);
    prefill_kernel<<<TT, 1024>>>();
    pre0_kernel<<<128, 256>>>(w_ih0, z);

    const size_t LQ = (size_t)NG * 4096;   // bytes per layer of q8 weights

    // layer 0 -> hsA
    lstm_layer_kernel<<<GRID, PBLOCK, SMEM_DYN>>>(q8_p, s_hh_p, hsA_p);
    // layer 1: pre = hsA @ w_ih_r[0]^T + bias1 ; -> hsB
    gemm_pre_kernel<<<ggrid, 256>>>(hsA_p, w_ih_r, bias_p + 1 * NG);
    lstm_layer_kernel<<<GRID, PBLOCK, SMEM_DYN>>>(q8_p + 1 * LQ, s_hh_p + 1 * NG, hsB_p);
    // layer 2
    gemm_pre_kernel<<<ggrid, 256>>>(hsB_p, w_ih_r + (size_t)1 * NG * NH, bias_p + 2 * NG);
    lstm_layer_kernel<<<GRID, PBLOCK, SMEM_DYN>>>(q8_p + 2 * LQ, s_hh_p + 2 * NG, hsA_p);
    // layer 3
    gemm_pre_kernel<<<ggrid, 256>>>(hsA_p, w_ih_r + (size_t)2 * NG * NH, bias_p + 3 * NG);
    lstm_layer_kernel<<<GRID, PBLOCK, SMEM_DYN>>>(q8_p + 3 * LQ, s_hh_p + 3 * NG, hsB_p);

    proj_kernel<<<TT, 256>>>(w_sp, b_sp, out);
}

// round 13
// speedup vs baseline: 1.6431x; 1.1986x over previous
#include <cuda_runtime.h>
#include <math.h>
#include <stdint.h>

// Problem constants
#define NZ   256
#define NH   2048
#define NG   8192      // 4*NH gate rows
#define TT   256       // timesteps
#define KF4  (NH/4)    // 512 float4 per h-vector
#define PBLOCK 512               // 16 warps: one warp per hidden unit (full row)
#define UPB    16                // hidden units per block
#define GRID   (NH/UPB)          // 128 blocks
#define KQ4    256               // uint4 per q8 row (4096 bytes: 2048 hi + 2048 lo)
#define GSQ    (NH * KQ4)        // uint4 stride between gate blocks

// dynamic smem: [0,64K) gate-g q8 weights; [64K,68K) h int8 (512 hi + 512 lo int32)
#define SMW_BYTES  (UPB * KQ4 * 16)            // 65536
#define SMH_OFF    (SMW_BYTES)
#define SMEM_DYN   (SMH_OFF + 4096)            // 69632 bytes

// ---------------- device scratch (no allocations allowed) ----------------
__device__ float g_bias[4][NG];          // b_ih + b_hh per layer
__device__ float g_pre[TT * NG];         // per-layer precomputed ih gates (+bias), 8.4MB
__device__ float g_hsA[TT * NH];         // ping-pong hidden-sequence buffers (fp32, GEMM food)
__device__ float g_hsB[TT * NH];
__device__ unsigned g_count;             // grid barrier (returns to 0)
__device__ unsigned g_sense;             // parity; 256 flips/launch (even) -> replay-safe
__device__ unsigned short g_hq8[2][NH];  // packed h int8 (q1 | q2<<8), parity double-buffer

// dual-int8 hh weights, all 4 layers. Row layout (4096B): bytes[0,2048)=q1 planes
// packed 4/int32, bytes[2048,4096)=q2. W = (m/127)*(q1 + q2/254), per-row max m.
__device__ unsigned char q8_hh[(size_t)4 * NG * 4096];   // 134 MB
__device__ float s_hh[4 * NG];           // per-row raw max m

// HW tanh (max err ~1e-5); sigmoid via exact identity
__device__ __forceinline__ float tanh_fast(float x) {
    float y;
    asm("tanh.approx.f32 %0, %1;" : "=f"(y) : "f"(x));
    return y;
}
__device__ __forceinline__ float sigf(float x) {
    return fmaf(0.5f, tanh_fast(0.5f * x), 0.5f);
}

// 12 dp4a: hi*hi -> ah ; hi*lo + lo*hi -> am  (lo*lo dropped, rel ~6e-5)
#define DP4ACC(ah, am, whi, wlo, hh, hl)                       \
    do {                                                       \
        ah = __dp4a((int)(whi).x, (int)(hh).x, ah);            \
        ah = __dp4a((int)(whi).y, (int)(hh).y, ah);            \
        ah = __dp4a((int)(whi).z, (int)(hh).z, ah);            \
        ah = __dp4a((int)(whi).w, (int)(hh).w, ah);            \
        am = __dp4a((int)(whi).x, (int)(hl).x, am);            \
        am = __dp4a((int)(whi).y, (int)(hl).y, am);            \
        am = __dp4a((int)(whi).z, (int)(hl).z, am);            \
        am = __dp4a((int)(whi).w, (int)(hl).w, am);            \
        am = __dp4a((int)(wlo).x, (int)(hh).x, am);            \
        am = __dp4a((int)(wlo).y, (int)(hh).y, am);            \
        am = __dp4a((int)(wlo).z, (int)(hh).z, am);            \
        am = __dp4a((int)(wlo).w, (int)(hh).w, am);            \
    } while (0)

// ---------------- prologue: summed biases ----------------
__global__ void bias_kernel(const float* __restrict__ bi0, const float* __restrict__ bh0,
                            const float* __restrict__ bir, const float* __restrict__ bhr) {
    int idx = blockIdx.x * blockDim.x + threadIdx.x;   // 4*NG threads
    if (idx < 4 * NG) {
        int l = idx >> 13;
        int r = idx & (NG - 1);
        float v = (l == 0) ? (bi0[r] + bh0[r])
                           : (bir[(size_t)(l - 1) * NG + r] + bhr[(size_t)(l - 1) * NG + r]);
        g_bias[l][r] = v;
    }
}

// ---------------- prologue: quantize the 4 hh matrices to dual-int8 ----------------
__global__ void quant_kernel(const float* __restrict__ whh0,
                             const float* __restrict__ whhr) {
    int gw   = (blockIdx.x * blockDim.x + threadIdx.x) >> 5;
    int lane = threadIdx.x & 31;
    int nw   = (gridDim.x * blockDim.x) >> 5;
    for (int r = gw; r < 4 * NG; r += nw) {
        int l  = r >> 13;
        int rr = r & (NG - 1);
        const float* src = (l == 0) ? whh0 + (size_t)rr * NH
                                    : whhr + ((size_t)(l - 1) * NG + rr) * NH;
        const float4* s4 = (const float4*)src;
        float m = 0.f;
        #pragma unroll 4
        for (int i = lane; i < KF4; i += 32) {
            float4 v = s4[i];
            m = fmaxf(m, fmaxf(fmaxf(fabsf(v.x), fabsf(v.y)), fmaxf(fabsf(v.z), fabsf(v.w))));
        }
        #pragma unroll
        for (int o = 16; o; o >>= 1) m = fmaxf(m, __shfl_xor_sync(0xffffffffu, m, o));
        float qs = (m > 0.f) ? 127.0f / m : 0.f;
        if (lane == 0) s_hh[r] = m;            // raw max; scale folded in epilogue
        int* d32 = (int*)(q8_hh + (size_t)r * 4096);
        #pragma unroll 4
        for (int i = lane; i < KF4; i += 32) {   // one int32 = 4 weights
            float4 v = s4[i];
            float x0 = v.x * qs, x1 = v.y * qs, x2 = v.z * qs, x3 = v.w * qs;
            int a0 = __float2int_rn(x0), a1 = __float2int_rn(x1);
            int a2 = __float2int_rn(x2), a3 = __float2int_rn(x3);
            int b0 = __float2int_rn((x0 - (float)a0) * 254.f);
            int b1 = __float2int_rn((x1 - (float)a1) * 254.f);
            int b2 = __float2int_rn((x2 - (float)a2) * 254.f);
            int b3 = __float2int_rn((x3 - (float)a3) * 254.f);
            d32[i]       = (a0 & 0xff) | ((a1 & 0xff) << 8) | ((a2 & 0xff) << 16) | ((a3 & 0xff) << 24);
            d32[512 + i] = (b0 & 0xff) | ((b1 & 0xff) << 8) | ((b2 & 0xff) << 16) | ((b3 & 0xff) << 24);
        }
    }
}

// ---------------- prologue: g_pre[t][r] = bias0[r] for all t (layer0 default) -------
__global__ void prefill_kernel() {
    int t = blockIdx.x;
    for (int r = threadIdx.x; r < NG; r += blockDim.x)
        g_pre[(size_t)t * NG + r] = g_bias[0][r];
}

// ---------------- prologue: overwrite t=0 with z @ W_ih0^T + bias0 ----------------
__global__ void pre0_kernel(const float* __restrict__ wih0, const float* __restrict__ z) {
    int gw   = (blockIdx.x * blockDim.x + threadIdx.x) >> 5;
    int lane = threadIdx.x & 31;
    int nw   = (gridDim.x * blockDim.x) >> 5;
    for (int row = gw; row < NG; row += nw) {
        const float* wr = wih0 + (size_t)row * NZ;
        float s = 0.f;
        for (int k = lane; k < NZ; k += 32) s += wr[k] * z[k];
        #pragma unroll
        for (int o = 16; o; o >>= 1) s += __shfl_xor_sync(0xffffffffu, s, o);
        if (lane == 0) g_pre[row] = s + g_bias[0][row];
    }
}

// ---------------- per-layer ih GEMM: pre[t][row] = X[t]·W[row] + bias[row] ----------
#define GBK 16
__global__ void __launch_bounds__(256, 1)
gemm_pre_kernel(const float* __restrict__ X,
                const float* __restrict__ Wf,
                const float* __restrict__ bias) {
    __shared__ float Xs[GBK][132];
    __shared__ float Ws[GBK][132];
    const int tid = threadIdx.x;
    const int rb  = blockIdx.x * 128;
    const int tb  = blockIdx.y * 128;
    const int tx  = tid & 15, ty = tid >> 4;

    float acc[8][8];
    #pragma unroll
    for (int i = 0; i < 8; ++i)
        #pragma unroll
        for (int j = 0; j < 8; ++j) acc[i][j] = 0.f;

    float4 px[2], pw[2];
    #pragma unroll
    for (int r = 0; r < 2; ++r) {
        int idx = tid + r * 256;
        int tt  = idx >> 2;
        int k4  = idx & 3;
        px[r] = *(const float4*)(X  + (size_t)(tb + tt) * NH + k4 * 4);
        pw[r] = *(const float4*)(Wf + (size_t)(rb + tt) * NH + k4 * 4);
    }

    for (int kk = 0; kk < NH; kk += GBK) {
        __syncthreads();
        #pragma unroll
        for (int r = 0; r < 2; ++r) {
            int idx = tid + r * 256;
            int tt  = idx >> 2;
            int k0  = (idx & 3) * 4;
            Xs[k0 + 0][tt] = px[r].x; Xs[k0 + 1][tt] = px[r].y;
            Xs[k0 + 2][tt] = px[r].z; Xs[k0 + 3][tt] = px[r].w;
            Ws[k0 + 0][tt] = pw[r].x; Ws[k0 + 1][tt] = pw[r].y;
            Ws[k0 + 2][tt] = pw[r].z; Ws[k0 + 3][tt] = pw[r].w;
        }
        __syncthreads();
        if (kk + GBK < NH) {
            #pragma unroll
            for (int r = 0; r < 2; ++r) {
                int idx = tid + r * 256;
                int tt  = idx >> 2;
                int k4  = idx & 3;
                px[r] = *(const float4*)(X  + (size_t)(tb + tt) * NH + kk + GBK + k4 * 4);
                pw[r] = *(const float4*)(Wf + (size_t)(rb + tt) * NH + kk + GBK + k4 * 4);
            }
        }
        #pragma unroll
        for (int k = 0; k < GBK; ++k) {
            float4 x0 = *(const float4*)&Xs[k][ty * 8];
            float4 x1 = *(const float4*)&Xs[k][ty * 8 + 4];
            float4 w0 = *(const float4*)&Ws[k][tx * 8];
            float4 w1 = *(const float4*)&Ws[k][tx * 8 + 4];
            float xr[8] = {x0.x, x0.y, x0.z, x0.w, x1.x, x1.y, x1.z, x1.w};
            float wr[8] = {w0.x, w0.y, w0.z, w0.w, w1.x, w1.y, w1.z, w1.w};
            #pragma unroll
            for (int i = 0; i < 8; ++i)
                #pragma unroll
                for (int j = 0; j < 8; ++j)
                    acc[i][j] = fmaf(xr[i], wr[j], acc[i][j]);
        }
    }

    const float4 b0 = *(const float4*)&bias[rb + tx * 8];
    const float4 b1 = *(const float4*)&bias[rb + tx * 8 + 4];
    #pragma unroll
    for (int i = 0; i < 8; ++i) {
        float* cp = g_pre + (size_t)(tb + ty * 8 + i) * NG + rb + tx * 8;
        float4 v0 = make_float4(acc[i][0] + b0.x, acc[i][1] + b0.y,
                                acc[i][2] + b0.z, acc[i][3] + b0.w);
        float4 v1 = make_float4(acc[i][4] + b1.x, acc[i][5] + b1.y,
                                acc[i][6] + b1.z, acc[i][7] + b1.w);
        *(float4*)cp       = v0;
        *(float4*)(cp + 4) = v1;
    }
}

// ---------------- R8 grid barrier: single atomic arrival + relaxed spin -------------
__device__ __forceinline__ void grid_barrier(unsigned& sense) {
    __syncthreads();
    if (threadIdx.x == 0) {
        unsigned s = sense ^ 1u;
        sense = s;
        unsigned old;
        asm volatile("atom.release.gpu.global.add.u32 %0, [%1], %2;"
                     : "=r"(old) : "l"(&g_count), "r"(1u) : "memory");
        if (old == (unsigned)(GRID - 1)) {
            asm volatile("st.relaxed.gpu.global.u32 [%0], %1;"
                         :: "l"(&g_count), "r"(0u) : "memory");
            asm volatile("st.release.gpu.global.u32 [%0], %1;"
                         :: "l"(&g_sense), "r"(s) : "memory");
        } else {
            unsigned v;
            do {
                asm volatile("ld.relaxed.gpu.global.u32 %0, [%1];"
                             : "=r"(v) : "l"(&g_sense) : "memory");
            } while (v != s);
        }
    }
    __syncthreads();
}

// ---------------- per-layer persistent step kernel (dual-int8 dp4a) ----------------
// 128 blocks x 512 threads; one warp = one full hidden unit. 128 regs/thread.
// Gate routing: i,f -> REGISTERS (loaded once per layer, 64 regs/lane);
//               g   -> SMEM (preloaded once, 64KB);
//               o   -> L1-pinned __ldg (64KB/block << L1).
// h carried between steps as packed int8 pairs in g_hq8 (parity double-buffered).
__global__ void __launch_bounds__(PBLOCK, 1)
lstm_layer_kernel(const unsigned char* __restrict__ Wq,  // layer q8 base
                  const float* __restrict__ scl,         // per-row raw max [NG]
                  float* __restrict__ out) {             // [TT][NH] fp32 hidden out
    extern __shared__ char smem_dyn[];
    uint4* smW    = (uint4*)smem_dyn;                    // [UPB*KQ4] gate-g weights
    int*   smh_hi = (int*)(smem_dyn + SMH_OFF);          // [512] packed q1 of h
    int*   smh_lo = smh_hi + 512;                        // [512] packed q2 of h

    const int tid  = threadIdx.x;
    const int lane = tid & 31;
    const int widx = tid >> 5;        // 0..15 = unit within block
    const int u    = blockIdx.x * UPB + widx;
    const uint4* W = (const uint4*)Wq + (size_t)u * KQ4;

    // preload gate-g (index 2) q8 rows for this block's 16 units into SMEM
    {
        const uint4* Wg = (const uint4*)Wq + (size_t)2 * GSQ;
        for (int i = tid; i < UPB * KQ4; i += PBLOCK) {
            int unit = i >> 8;                  // /KQ4
            int j    = i & (KQ4 - 1);
            smW[i] = __ldcg(Wg + (size_t)(blockIdx.x * UPB + unit) * KQ4 + j);
        }
    }
    const uint4* smWme = smW + widx * KQ4;

    // gates i,f -> registers: 16 x uint4 per lane (64 regs), loaded once per layer
    uint4 wih[4], wil[4], wfh[4], wfl[4];
    #pragma unroll
    for (int it = 0; it < 4; ++it) {
        const int j = lane + it * 32;
        wih[it] = __ldcg(W + j);
        wil[it] = __ldcg(W + 128 + j);
        wfh[it] = __ldcg(W + GSQ + j);
        wfl[it] = __ldcg(W + GSQ + 128 + j);
    }

    // dequant scales folded with 1/127^2 (W plane) ; h scale 1/127 folded too
    const float fold = 1.f / 16129.f;          // 1/(127*127)
    const float sc0 = scl[u]          * fold;
    const float sc1 = scl[NH + u]     * fold;
    const float sc2 = scl[2 * NH + u] * fold;
    const float sc3 = scl[3 * NH + u] * fold;

    unsigned sense = 0;
    float c = 0.f;                    // cell state (lane 0)

    for (int t = 0; t < TT; ++t) {
        float p0 = 0.f, p1 = 0.f, p2 = 0.f, p3 = 0.f;
        if (lane == 0) {
            const float* pt = g_pre + (size_t)t * NG;
            p0 = __ldcg(pt + u);
            p1 = __ldcg(pt + NH + u);
            p2 = __ldcg(pt + 2 * NH + u);
            p3 = __ldcg(pt + 3 * NH + u);
        }
        // stage h_{t-1} int8: 512 threads, one int2 (4 packed shorts) each
        if (t > 0) {
            const int2* src = (const int2*)g_hq8[(t - 1) & 1];
            int2 v = __ldcg(src + tid);
            smh_hi[tid] = __byte_perm(v.x, v.y, 0x6420);   // q1 bytes
            smh_lo[tid] = __byte_perm(v.x, v.y, 0x7531);   // q2 bytes
        } else {
            smh_hi[tid] = 0;
            smh_lo[tid] = 0;
        }
        __syncthreads();   // also covers smW preload before first use

        int ah0 = 0, am0 = 0, ah1 = 0, am1 = 0;
        int ah2 = 0, am2 = 0, ah3 = 0, am3 = 0;
        const uint4* Hhi4 = (const uint4*)smh_hi;
        const uint4* Hlo4 = (const uint4*)smh_lo;
        #pragma unroll
        for (int it = 0; it < 4; ++it) {
            const int j = lane + it * 32;        // 0..127
            const uint4 hh = Hhi4[j];
            const uint4 hl = Hlo4[j];
            DP4ACC(ah0, am0, wih[it], wil[it], hh, hl);    // gate i (registers)
            DP4ACC(ah1, am1, wfh[it], wfl[it], hh, hl);    // gate f (registers)
            uint4 w = smWme[j];
            uint4 x = smWme[128 + j];                      // gate g (SMEM)
            DP4ACC(ah2, am2, w, x, hh, hl);
            w = __ldg(W + 3 * GSQ + j);
            x = __ldg(W + 3 * GSQ + 128 + j);              // gate o (L1-pinned)
            DP4ACC(ah3, am3, w, x, hh, hl);
        }

        float d0 = fmaf((float)am0, 1.f / 254.f, (float)ah0);
        float d1 = fmaf((float)am1, 1.f / 254.f, (float)ah1);
        float d2 = fmaf((float)am2, 1.f / 254.f, (float)ah2);
        float d3 = fmaf((float)am3, 1.f / 254.f, (float)ah3);
        #pragma unroll
        for (int o = 16; o; o >>= 1) {
            d0 += __shfl_xor_sync(0xffffffffu, d0, o);
            d1 += __shfl_xor_sync(0xffffffffu, d1, o);
            d2 += __shfl_xor_sync(0xffffffffu, d2, o);
            d3 += __shfl_xor_sync(0xffffffffu, d3, o);
        }

        if (lane == 0) {
            float ig = fmaf(d0, sc0, p0);
            float fg = fmaf(d1, sc1, p1);
            float gg = fmaf(d2, sc2, p2);
            float og = fmaf(d3, sc3, p3);
            c = sigf(fg) * c + sigf(ig) * tanh_fast(gg);
            float h = sigf(og) * tanh_fast(c);
            out[(size_t)t * NH + u] = h;
            // quantize h for the next step: h in (-1,1) -> q1 + q2/254 over /127
            float x = h * 127.f;
            int q1 = __float2int_rn(x);
            int q2 = __float2int_rn((x - (float)q1) * 254.f);
            unsigned short pk = (unsigned short)((q1 & 0xff) | ((q2 & 0xff) << 8));
            unsigned short* hp = &g_hq8[t & 1][u];
            asm volatile("st.global.cg.u16 [%0], %1;" :: "l"(hp), "h"(pk) : "memory");
        }

        grid_barrier(sense);   // 256 flips per launch (even parity: replay-safe)
    }
}

// ---------------- epilogue: states[t] = h3[t] @ w_sp^T + b_sp ----------------
__global__ void proj_kernel(const float* __restrict__ wsp, const float* __restrict__ bsp,
                            float* __restrict__ out) {
    __shared__ float4 shh[KF4];
    const int t = blockIdx.x;
    const int tid = threadIdx.x;    // 256 threads
    const float4* h4 = (const float4*)g_hsB + (size_t)t * KF4;  // layer3 output in B
    shh[tid]       = h4[tid];
    shh[tid + 256] = h4[tid + 256];
    __syncthreads();
    const int widx = tid >> 5, lane = tid & 31;
    for (int o = widx; o < 64; o += 8) {
        const float4* wr = (const float4*)wsp + (size_t)o * KF4;
        float s = 0.f;
        #pragma unroll 4
        for (int i = lane; i < KF4; i += 32) {
            float4 w = __ldg(wr + i);
            float4 hv = shh[i];
            s += w.x * hv.x + w.y * hv.y + w.z * hv.z + w.w * hv.w;
        }
        #pragma unroll
        for (int off = 16; off; off >>= 1) s += __shfl_xor_sync(0xffffffffu, s, off);
        if (lane == 0) out[(size_t)t * 64 + o] = s + bsp[o];
    }
}

// ---------------- launch ----------------
extern "C" void kernel_launch(void* const* d_in, const int* in_sizes, int n_in,
                              void* d_out, int out_size) {
    const float* z      = (const float*)d_in[0];
    const float* w_ih0  = (const float*)d_in[1];
    const float* w_hh0  = (const float*)d_in[2];
    const float* b_ih0  = (const float*)d_in[3];
    const float* b_hh0  = (const float*)d_in[4];
    const float* w_ih_r = (const float*)d_in[5];
    const float* w_hh_r = (const float*)d_in[6];
    const float* b_ih_r = (const float*)d_in[7];
    const float* b_hh_r = (const float*)d_in[8];
    const float* w_sp   = (const float*)d_in[9];
    const float* b_sp   = (const float*)d_in[10];
    float* out = (float*)d_out;

    static unsigned char* q8_p = nullptr;
    static float* s_hh_p = nullptr;
    static float* bias_p = nullptr;
    static float* hsA_p = nullptr;
    static float* hsB_p = nullptr;
    if (!q8_p) {
        cudaGetSymbolAddress((void**)&q8_p, q8_hh);
        cudaGetSymbolAddress((void**)&s_hh_p, s_hh);
        cudaGetSymbolAddress((void**)&bias_p, g_bias);
        cudaGetSymbolAddress((void**)&hsA_p, g_hsA);
        cudaGetSymbolAddress((void**)&hsB_p, g_hsB);
        cudaFuncSetAttribute(lstm_layer_kernel,
                             cudaFuncAttributeMaxDynamicSharedMemorySize, SMEM_DYN);
        // ~68KB smem; rest is L1 for the pinned gate-o rows (64KB/block)
        cudaFuncSetAttribute(lstm_layer_kernel,
                             cudaFuncAttributePreferredSharedMemoryCarveout, 32);
    }

    dim3 ggrid(NG / 128, TT / 128);   // 64 x 2 = 128 blocks (one wave)

    bias_kernel<<<64, 512>>>(b_ih0, b_hh0, b_ih_r, b_hh_r);
    quant_kernel<<<448, 512>>>(w_hh0, w_hh_r);
    prefill_kernel<<<TT, 1024>>>();
    pre0_kernel<<<128, 256>>>(w_ih0, z);

    const size_t LQ = (size_t)NG * 4096;   // bytes per layer of q8 weights

    // layer 0 -> hsA
    lstm_layer_kernel<<<GRID, PBLOCK, SMEM_DYN>>>(q8_p, s_hh_p, hsA_p);
    // layer 1: pre = hsA @ w_ih_r[0]^T + bias1 ; -> hsB
    gemm_pre_kernel<<<ggrid, 256>>>(hsA_p, w_ih_r, bias_p + 1 * NG);
    lstm_layer_kernel<<<GRID, PBLOCK, SMEM_DYN>>>(q8_p + 1 * LQ, s_hh_p + 1 * NG, hsB_p);
    // layer 2
    gemm_pre_kernel<<<ggrid, 256>>>(hsB_p, w_ih_r + (size_t)1 * NG * NH, bias_p + 2 * NG);
    lstm_layer_kernel<<<GRID, PBLOCK, SMEM_DYN>>>(q8_p + 2 * LQ, s_hh_p + 2 * NG, hsA_p);
    // layer 3
    gemm_pre_kernel<<<ggrid, 256>>>(hsA_p, w_ih_r + (size_t)2 * NG * NH, bias_p + 3 * NG);
    lstm_layer_kernel<<<GRID, PBLOCK, SMEM_DYN>>>(q8_p + 3 * LQ, s_hh_p + 3 * NG, hsB_p);

    proj_kernel<<<TT, 256>>>(w_sp, b_sp, out);
}

// round 16
// speedup vs baseline: 1.6678x; 1.0150x over previous
#include <cuda_runtime.h>
#include <math.h>
#include <stdint.h>

// Problem constants
#define NZ   256
#define NH   2048
#define NG   8192      // 4*NH gate rows
#define TT   256       // timesteps
#define KF4  (NH/4)    // 512 float4 per h-vector
#define PBLOCK 512               // 16 warps: one warp per hidden unit (full row)
#define UPB    16                // hidden units per block
#define GRID   (NH/UPB)          // 128 blocks
#define KQ4    256               // uint4 per q8 row (4096 bytes: 2048 hi + 2048 lo)
#define GSQ    (NH * KQ4)        // uint4 stride between gate blocks

// dynamic smem: [0,128K) gate-g + gate-o q8 weights; [128K,132K) h staging (hi+lo)
#define SMW_U4    (UPB * KQ4)                  // uint4 count per gate bank (4096)
#define SMW_BYTES (SMW_U4 * 16 * 2)            // 131072 (g bank + o bank)
#define SMH_OFF   (SMW_BYTES)
#define SMEM_DYN  (SMH_OFF + 4096)             // 135168 bytes (< 227KB limit)

// ---------------- device scratch (no allocations allowed) ----------------
__device__ float g_bias[4][NG];          // b_ih + b_hh per layer
__device__ float g_pre[TT * NG];         // per-layer precomputed ih gates (+bias), 8.4MB
__device__ float g_hsA[TT * NH];         // ping-pong hidden-sequence buffers (fp32, GEMM food)
__device__ float g_hsB[TT * NH];
__device__ unsigned g_count;             // grid barrier (returns to 0)
__device__ unsigned g_sense;             // parity; 256 flips/launch (even) -> replay-safe
__device__ unsigned short g_hq8[2][NH];  // packed h int8 (q1 | q2<<8), parity double-buffer

// dual-int8 hh weights, all 4 layers. Row layout (4096B): bytes[0,2048)=q1 planes
// packed 4/int32, bytes[2048,4096)=q2. W = (m/127)*(q1 + q2/254), per-row max m.
__device__ unsigned char q8_hh[(size_t)4 * NG * 4096];   // 134 MB
__device__ float s_hh[4 * NG];           // per-row raw max m

// HW tanh (max err ~1e-5); sigmoid via exact identity
__device__ __forceinline__ float tanh_fast(float x) {
    float y;
    asm("tanh.approx.f32 %0, %1;" : "=f"(y) : "f"(x));
    return y;
}
__device__ __forceinline__ float sigf(float x) {
    return fmaf(0.5f, tanh_fast(0.5f * x), 0.5f);
}

// 12 dp4a: hi*hi -> ah ; hi*lo + lo*hi -> am  (lo*lo dropped, rel ~6e-5)
#define DP4ACC(ah, am, whi, wlo, hh, hl)                       \
    do {                                                       \
        ah = __dp4a((int)(whi).x, (int)(hh).x, ah);            \
        ah = __dp4a((int)(whi).y, (int)(hh).y, ah);            \
        ah = __dp4a((int)(whi).z, (int)(hh).z, ah);            \
        ah = __dp4a((int)(whi).w, (int)(hh).w, ah);            \
        am = __dp4a((int)(whi).x, (int)(hl).x, am);            \
        am = __dp4a((int)(whi).y, (int)(hl).y, am);            \
        am = __dp4a((int)(whi).z, (int)(hl).z, am);            \
        am = __dp4a((int)(whi).w, (int)(hl).w, am);            \
        am = __dp4a((int)(wlo).x, (int)(hh).x, am);            \
        am = __dp4a((int)(wlo).y, (int)(hh).y, am);            \
        am = __dp4a((int)(wlo).z, (int)(hh).z, am);            \
        am = __dp4a((int)(wlo).w, (int)(hh).w, am);            \
    } while (0)

// ---------------- prologue: summed biases ----------------
__global__ void bias_kernel(const float* __restrict__ bi0, const float* __restrict__ bh0,
                            const float* __restrict__ bir, const float* __restrict__ bhr) {
    int idx = blockIdx.x * blockDim.x + threadIdx.x;   // 4*NG threads
    if (idx < 4 * NG) {
        int l = idx >> 13;
        int r = idx & (NG - 1);
        float v = (l == 0) ? (bi0[r] + bh0[r])
                           : (bir[(size_t)(l - 1) * NG + r] + bhr[(size_t)(l - 1) * NG + r]);
        g_bias[l][r] = v;
    }
}

// ---------------- prologue: quantize the 4 hh matrices to dual-int8 ----------------
__global__ void quant_kernel(const float* __restrict__ whh0,
                             const float* __restrict__ whhr) {
    int gw   = (blockIdx.x * blockDim.x + threadIdx.x) >> 5;
    int lane = threadIdx.x & 31;
    int nw   = (gridDim.x * blockDim.x) >> 5;
    for (int r = gw; r < 4 * NG; r += nw) {
        int l  = r >> 13;
        int rr = r & (NG - 1);
        const float* src = (l == 0) ? whh0 + (size_t)rr * NH
                                    : whhr + ((size_t)(l - 1) * NG + rr) * NH;
        const float4* s4 = (const float4*)src;
        float m = 0.f;
        #pragma unroll 4
        for (int i = lane; i < KF4; i += 32) {
            float4 v = s4[i];
            m = fmaxf(m, fmaxf(fmaxf(fabsf(v.x), fabsf(v.y)), fmaxf(fabsf(v.z), fabsf(v.w))));
        }
        #pragma unroll
        for (int o = 16; o; o >>= 1) m = fmaxf(m, __shfl_xor_sync(0xffffffffu, m, o));
        float qs = (m > 0.f) ? 127.0f / m : 0.f;
        if (lane == 0) s_hh[r] = m;            // raw max; scale folded in epilogue
        int* d32 = (int*)(q8_hh + (size_t)r * 4096);
        #pragma unroll 4
        for (int i = lane; i < KF4; i += 32) {   // one int32 = 4 weights
            float4 v = s4[i];
            float x0 = v.x * qs, x1 = v.y * qs, x2 = v.z * qs, x3 = v.w * qs;
            int a0 = __float2int_rn(x0), a1 = __float2int_rn(x1);
            int a2 = __float2int_rn(x2), a3 = __float2int_rn(x3);
            int b0 = __float2int_rn((x0 - (float)a0) * 254.f);
            int b1 = __float2int_rn((x1 - (float)a1) * 254.f);
            int b2 = __float2int_rn((x2 - (float)a2) * 254.f);
            int b3 = __float2int_rn((x3 - (float)a3) * 254.f);
            d32[i]       = (a0 & 0xff) | ((a1 & 0xff) << 8) | ((a2 & 0xff) << 16) | ((a3 & 0xff) << 24);
            d32[512 + i] = (b0 & 0xff) | ((b1 & 0xff) << 8) | ((b2 & 0xff) << 16) | ((b3 & 0xff) << 24);
        }
    }
}

// ---------------- prologue: g_pre[t][r] = bias0[r] for all t (layer0 default) -------
__global__ void prefill_kernel() {
    int t = blockIdx.x;
    for (int r = threadIdx.x; r < NG; r += blockDim.x)
        g_pre[(size_t)t * NG + r] = g_bias[0][r];
}

// ---------------- prologue: overwrite t=0 with z @ W_ih0^T + bias0 ----------------
__global__ void pre0_kernel(const float* __restrict__ wih0, const float* __restrict__ z) {
    int gw   = (blockIdx.x * blockDim.x + threadIdx.x) >> 5;
    int lane = threadIdx.x & 31;
    int nw   = (gridDim.x * blockDim.x) >> 5;
    for (int row = gw; row < NG; row += nw) {
        const float* wr = wih0 + (size_t)row * NZ;
        float s = 0.f;
        for (int k = lane; k < NZ; k += 32) s += wr[k] * z[k];
        #pragma unroll
        for (int o = 16; o; o >>= 1) s += __shfl_xor_sync(0xffffffffu, s, o);
        if (lane == 0) g_pre[row] = s + g_bias[0][row];
    }
}

// ---------------- per-layer ih GEMM: pre[t][row] = X[t]·W[row] + bias[row] ----------
#define GBK 16
__global__ void __launch_bounds__(256, 1)
gemm_pre_kernel(const float* __restrict__ X,
                const float* __restrict__ Wf,
                const float* __restrict__ bias) {
    __shared__ float Xs[GBK][132];
    __shared__ float Ws[GBK][132];
    const int tid = threadIdx.x;
    const int rb  = blockIdx.x * 128;
    const int tb  = blockIdx.y * 128;
    const int tx  = tid & 15, ty = tid >> 4;

    float acc[8][8];
    #pragma unroll
    for (int i = 0; i < 8; ++i)
        #pragma unroll
        for (int j = 0; j < 8; ++j) acc[i][j] = 0.f;

    float4 px[2], pw[2];
    #pragma unroll
    for (int r = 0; r < 2; ++r) {
        int idx = tid + r * 256;
        int tt  = idx >> 2;
        int k4  = idx & 3;
        px[r] = *(const float4*)(X  + (size_t)(tb + tt) * NH + k4 * 4);
        pw[r] = *(const float4*)(Wf + (size_t)(rb + tt) * NH + k4 * 4);
    }

    for (int kk = 0; kk < NH; kk += GBK) {
        __syncthreads();
        #pragma unroll
        for (int r = 0; r < 2; ++r) {
            int idx = tid + r * 256;
            int tt  = idx >> 2;
            int k0  = (idx & 3) * 4;
            Xs[k0 + 0][tt] = px[r].x; Xs[k0 + 1][tt] = px[r].y;
            Xs[k0 + 2][tt] = px[r].z; Xs[k0 + 3][tt] = px[r].w;
            Ws[k0 + 0][tt] = pw[r].x; Ws[k0 + 1][tt] = pw[r].y;
            Ws[k0 + 2][tt] = pw[r].z; Ws[k0 + 3][tt] = pw[r].w;
        }
        __syncthreads();
        if (kk + GBK < NH) {
            #pragma unroll
            for (int r = 0; r < 2; ++r) {
                int idx = tid + r * 256;
                int tt  = idx >> 2;
                int k4  = idx & 3;
                px[r] = *(const float4*)(X  + (size_t)(tb + tt) * NH + kk + GBK + k4 * 4);
                pw[r] = *(const float4*)(Wf + (size_t)(rb + tt) * NH + kk + GBK + k4 * 4);
            }
        }
        #pragma unroll
        for (int k = 0; k < GBK; ++k) {
            float4 x0 = *(const float4*)&Xs[k][ty * 8];
            float4 x1 = *(const float4*)&Xs[k][ty * 8 + 4];
            float4 w0 = *(const float4*)&Ws[k][tx * 8];
            float4 w1 = *(const float4*)&Ws[k][tx * 8 + 4];
            float xr[8] = {x0.x, x0.y, x0.z, x0.w, x1.x, x1.y, x1.z, x1.w};
            float wr[8] = {w0.x, w0.y, w0.z, w0.w, w1.x, w1.y, w1.z, w1.w};
            #pragma unroll
            for (int i = 0; i < 8; ++i)
                #pragma unroll
                for (int j = 0; j < 8; ++j)
                    acc[i][j] = fmaf(xr[i], wr[j], acc[i][j]);
        }
    }

    const float4 b0 = *(const float4*)&bias[rb + tx * 8];
    const float4 b1 = *(const float4*)&bias[rb + tx * 8 + 4];
    #pragma unroll
    for (int i = 0; i < 8; ++i) {
        float* cp = g_pre + (size_t)(tb + ty * 8 + i) * NG + rb + tx * 8;
        float4 v0 = make_float4(acc[i][0] + b0.x, acc[i][1] + b0.y,
                                acc[i][2] + b0.z, acc[i][3] + b0.w);
        float4 v1 = make_float4(acc[i][4] + b1.x, acc[i][5] + b1.y,
                                acc[i][6] + b1.z, acc[i][7] + b1.w);
        *(float4*)cp       = v0;
        *(float4*)(cp + 4) = v1;
    }
}

// ---------------- R8/R13 grid barrier: single atomic arrival + relaxed spin ---------
// atom.release orders this block's prior stores; spin is ld.relaxed (L2 read, no L1
// invalidate). Cross-block h data is read via __ldcg, so correctness holds.
__device__ __forceinline__ void grid_barrier(unsigned& sense) {
    __syncthreads();
    if (threadIdx.x == 0) {
        unsigned s = sense ^ 1u;
        sense = s;
        unsigned old;
        asm volatile("atom.release.gpu.global.add.u32 %0, [%1], %2;"
                     : "=r"(old) : "l"(&g_count), "r"(1u) : "memory");
        if (old == (unsigned)(GRID - 1)) {
            asm volatile("st.relaxed.gpu.global.u32 [%0], %1;"
                         :: "l"(&g_count), "r"(0u) : "memory");
            asm volatile("st.release.gpu.global.u32 [%0], %1;"
                         :: "l"(&g_sense), "r"(s) : "memory");
        } else {
            unsigned v;
            do {
                asm volatile("ld.relaxed.gpu.global.u32 %0, [%1];"
                             : "=r"(v) : "l"(&g_sense) : "memory");
            } while (v != s);
        }
    }
    __syncthreads();
}

// ---------------- per-layer persistent step kernel (dual-int8 dp4a) ----------------
// 128 blocks x 512 threads; one warp = one full hidden unit. 128 regs/thread.
// Gate routing: i,f -> REGISTERS (64 regs/lane, loaded once per layer);
//               g,o -> SMEM (preloaded once, 128KB, deterministic LDS latency --
//                      removes the per-step L2 weight stream and its barrier-taxed
//                      latency jitter, the R16 change).
// h carried between steps as packed int8 pairs in g_hq8 (parity double-buffered),
// synchronized by the proven R13 grid barrier.
__global__ void __launch_bounds__(PBLOCK, 1)
lstm_layer_kernel(const unsigned char* __restrict__ Wq,  // layer q8 base
                  const float* __restrict__ scl,         // per-row raw max [NG]
                  float* __restrict__ out) {             // [TT][NH] fp32 hidden out
    extern __shared__ char smem_dyn[];
    uint4* smW    = (uint4*)smem_dyn;                    // [2*SMW_U4]: g bank, o bank
    int*   smh_hi = (int*)(smem_dyn + SMH_OFF);          // [512] packed q1 of h
    int*   smh_lo = smh_hi + 512;                        // [512] packed q2 of h

    const int tid  = threadIdx.x;
    const int lane = tid & 31;
    const int widx = tid >> 5;        // 0..15 = unit within block
    const int u    = blockIdx.x * UPB + widx;
    const uint4* W = (const uint4*)Wq + (size_t)u * KQ4;

    // preload gate-g (index 2) and gate-o (index 3) q8 rows into SMEM
    {
        const uint4* Wg = (const uint4*)Wq + (size_t)2 * GSQ;
        const uint4* Wo = (const uint4*)Wq + (size_t)3 * GSQ;
        for (int i = tid; i < SMW_U4; i += PBLOCK) {
            int unit = i >> 8;                  // /KQ4
            int j    = i & (KQ4 - 1);
            size_t off = (size_t)(blockIdx.x * UPB + unit) * KQ4 + j;
            smW[i]          = __ldcg(Wg + off);
            smW[SMW_U4 + i] = __ldcg(Wo + off);
        }
    }
    const uint4* smWg = smW + widx * KQ4;            // this warp's gate-g row
    const uint4* smWo = smW + SMW_U4 + widx * KQ4;   // this warp's gate-o row

    // gates i,f -> registers: 16 x uint4 per lane (64 regs), loaded once per layer
    uint4 wih[4], wil[4], wfh[4], wfl[4];
    #pragma unroll
    for (int it = 0; it < 4; ++it) {
        const int j = lane + it * 32;
        wih[it] = __ldcg(W + j);
        wil[it] = __ldcg(W + 128 + j);
        wfh[it] = __ldcg(W + GSQ + j);
        wfl[it] = __ldcg(W + GSQ + 128 + j);
    }

    // dequant scales folded with 1/127^2 (W plane); h scale 1/127 folded too
    const float fold = 1.f / 16129.f;          // 1/(127*127)
    const float sc0 = scl[u]          * fold;
    const float sc1 = scl[NH + u]     * fold;
    const float sc2 = scl[2 * NH + u] * fold;
    const float sc3 = scl[3 * NH + u] * fold;

    unsigned sense = 0;
    float c = 0.f;                    // cell state (lane 0)

    for (int t = 0; t < TT; ++t) {
        float p0 = 0.f, p1 = 0.f, p2 = 0.f, p3 = 0.f;
        if (lane == 0) {
            const float* pt = g_pre + (size_t)t * NG;
            p0 = __ldcg(pt + u);
            p1 = __ldcg(pt + NH + u);
            p2 = __ldcg(pt + 2 * NH + u);
            p3 = __ldcg(pt + 3 * NH + u);
        }
        // stage h_{t-1} int8: 512 threads, one int2 (4 packed shorts) each
        if (t > 0) {
            const int2* src = (const int2*)g_hq8[(t - 1) & 1];
            int2 v = __ldcg(src + tid);
            smh_hi[tid] = __byte_perm(v.x, v.y, 0x6420);   // q1 bytes
            smh_lo[tid] = __byte_perm(v.x, v.y, 0x7531);   // q2 bytes
        } else {
            smh_hi[tid] = 0;
            smh_lo[tid] = 0;
        }
        __syncthreads();   // also covers smW preload before first use

        int ah0 = 0, am0 = 0, ah1 = 0, am1 = 0;
        int ah2 = 0, am2 = 0, ah3 = 0, am3 = 0;
        const uint4* Hhi4 = (const uint4*)smh_hi;
        const uint4* Hlo4 = (const uint4*)smh_lo;
        #pragma unroll
        for (int it = 0; it < 4; ++it) {
            const int j = lane + it * 32;        // 0..127
            const uint4 hh = Hhi4[j];
            const uint4 hl = Hlo4[j];
            DP4ACC(ah0, am0, wih[it], wil[it], hh, hl);    // gate i (registers)
            DP4ACC(ah1, am1, wfh[it], wfl[it], hh, hl);    // gate f (registers)
            uint4 w = smWg[j];
            uint4 x = smWg[128 + j];                       // gate g (SMEM)
            DP4ACC(ah2, am2, w, x, hh, hl);
            w = smWo[j];
            x = smWo[128 + j];                             // gate o (SMEM)
            DP4ACC(ah3, am3, w, x, hh, hl);
        }

        float d0 = fmaf((float)am0, 1.f / 254.f, (float)ah0);
        float d1 = fmaf((float)am1, 1.f / 254.f, (float)ah1);
        float d2 = fmaf((float)am2, 1.f / 254.f, (float)ah2);
        float d3 = fmaf((float)am3, 1.f / 254.f, (float)ah3);
        #pragma unroll
        for (int o = 16; o; o >>= 1) {
            d0 += __shfl_xor_sync(0xffffffffu, d0, o);
            d1 += __shfl_xor_sync(0xffffffffu, d1, o);
            d2 += __shfl_xor_sync(0xffffffffu, d2, o);
            d3 += __shfl_xor_sync(0xffffffffu, d3, o);
        }

        if (lane == 0) {
            float ig = fmaf(d0, sc0, p0);
            float fg = fmaf(d1, sc1, p1);
            float gg = fmaf(d2, sc2, p2);
            float og = fmaf(d3, sc3, p3);
            c = sigf(fg) * c + sigf(ig) * tanh_fast(gg);
            float h = sigf(og) * tanh_fast(c);
            out[(size_t)t * NH + u] = h;
            // quantize h for the next step: h in (-1,1) -> q1 + q2/254 over /127
            float x = h * 127.f;
            int q1 = __float2int_rn(x);
            int q2 = __float2int_rn((x - (float)q1) * 254.f);
            unsigned short pk = (unsigned short)((q1 & 0xff) | ((q2 & 0xff) << 8));
            unsigned short* hp = &g_hq8[t & 1][u];
            asm volatile("st.global.cg.u16 [%0], %1;" :: "l"(hp), "h"(pk) : "memory");
        }

        grid_barrier(sense);   // 256 flips per launch (even parity: replay-safe)
    }
}

// ---------------- epilogue: states[t] = h3[t] @ w_sp^T + b_sp ----------------
__global__ void proj_kernel(const float* __restrict__ wsp, const float* __restrict__ bsp,
                            float* __restrict__ out) {
    __shared__ float4 shh[KF4];
    const int t = blockIdx.x;
    const int tid = threadIdx.x;    // 256 threads
    const float4* h4 = (const float4*)g_hsB + (size_t)t * KF4;  // layer3 output in B
    shh[tid]       = h4[tid];
    shh[tid + 256] = h4[tid + 256];
    __syncthreads();
    const int widx = tid >> 5, lane = tid & 31;
    for (int o = widx; o < 64; o += 8) {
        const float4* wr = (const float4*)wsp + (size_t)o * KF4;
        float s = 0.f;
        #pragma unroll 4
        for (int i = lane; i < KF4; i += 32) {
            float4 w = __ldg(wr + i);
            float4 hv = shh[i];
            s += w.x * hv.x + w.y * hv.y + w.z * hv.z + w.w * hv.w;
        }
        #pragma unroll
        for (int off = 16; off; off >>= 1) s += __shfl_xor_sync(0xffffffffu, s, off);
        if (lane == 0) out[(size_t)t * 64 + o] = s + bsp[o];
    }
}

// ---------------- launch ----------------
extern "C" void kernel_launch(void* const* d_in, const int* in_sizes, int n_in,
                              void* d_out, int out_size) {
    const float* z      = (const float*)d_in[0];
    const float* w_ih0  = (const float*)d_in[1];
    const float* w_hh0  = (const float*)d_in[2];
    const float* b_ih0  = (const float*)d_in[3];
    const float* b_hh0  = (const float*)d_in[4];
    const float* w_ih_r = (const float*)d_in[5];
    const float* w_hh_r = (const float*)d_in[6];
    const float* b_ih_r = (const float*)d_in[7];
    const float* b_hh_r = (const float*)d_in[8];
    const float* w_sp   = (const float*)d_in[9];
    const float* b_sp   = (const float*)d_in[10];
    float* out = (float*)d_out;

    static unsigned char* q8_p = nullptr;
    static float* s_hh_p = nullptr;
    static float* bias_p = nullptr;
    static float* hsA_p = nullptr;
    static float* hsB_p = nullptr;
    if (!q8_p) {
        cudaGetSymbolAddress((void**)&q8_p, q8_hh);
        cudaGetSymbolAddress((void**)&s_hh_p, s_hh);
        cudaGetSymbolAddress((void**)&bias_p, g_bias);
        cudaGetSymbolAddress((void**)&hsA_p, g_hsA);
        cudaGetSymbolAddress((void**)&hsB_p, g_hsB);
        cudaFuncSetAttribute(lstm_layer_kernel,
                             cudaFuncAttributeMaxDynamicSharedMemorySize, SMEM_DYN);
        // ~132KB smem for weights; remaining L1 only needs the tiny staging stream
        cudaFuncSetAttribute(lstm_layer_kernel,
                             cudaFuncAttributePreferredSharedMemoryCarveout, 60);
    }

    dim3 ggrid(NG / 128, TT / 128);   // 64 x 2 = 128 blocks (one wave)

    bias_kernel<<<64, 512>>>(b_ih0, b_hh0, b_ih_r, b_hh_r);
    quant_kernel<<<448, 512>>>(w_hh0, w_hh_r);
    prefill_kernel<<<TT, 1024>>>();
    pre0_kernel<<<128, 256>>>(w_ih0, z);

    const size_t LQ = (size_t)NG * 4096;   // bytes per layer of q8 weights

    // layer 0 -> hsA
    lstm_layer_kernel<<<GRID, PBLOCK, SMEM_DYN>>>(q8_p, s_hh_p, hsA_p);
    // layer 1: pre = hsA @ w_ih_r[0]^T + bias1 ; -> hsB
    gemm_pre_kernel<<<ggrid, 256>>>(hsA_p, w_ih_r, bias_p + 1 * NG);
    lstm_layer_kernel<<<GRID, PBLOCK, SMEM_DYN>>>(q8_p + 1 * LQ, s_hh_p + 1 * NG, hsB_p);
    // layer 2
    gemm_pre_kernel<<<ggrid, 256>>>(hsB_p, w_ih_r + (size_t)1 * NG * NH, bias_p + 2 * NG);
    lstm_layer_kernel<<<GRID, PBLOCK, SMEM_DYN>>>(q8_p + 2 * LQ, s_hh_p + 2 * NG, hsA_p);
    // layer 3
    gemm_pre_kernel<<<ggrid, 256>>>(hsA_p, w_ih_r + (size_t)2 * NG * NH, bias_p + 3 * NG);
    lstm_layer_kernel<<<GRID, PBLOCK, SMEM_DYN>>>(q8_p + 3 * LQ, s_hh_p + 3 * NG, hsB_p);

    proj_kernel<<<TT, 256>>>(w_sp, b_sp, out);
}

// round 17
// speedup vs baseline: 1.7091x; 1.0248x over previous
#include <cuda_runtime.h>
#include <math.h>
#include <stdint.h>

// Problem constants
#define NZ   256
#define NH   2048
#define NG   8192      // 4*NH gate rows
#define TT   256       // timesteps
#define KF4  (NH/4)    // 512 float4 per h-vector
#define PBLOCK 512               // 16 warps: one warp per hidden unit (full row)
#define UPB    16                // hidden units per block
#define GRID   (NH/UPB)          // 128 blocks
#define KQ4    256               // uint4 per q8 row (4096 bytes: 2048 hi + 2048 lo)
#define GSQ    (NH * KQ4)        // uint4 stride between gate blocks

// dynamic smem: [0,128K) gate-g + gate-o q8 weights; [128K,132K) h staging (hi+lo)
#define SMW_U4    (UPB * KQ4)                  // uint4 count per gate bank (4096)
#define SMW_BYTES (SMW_U4 * 16 * 2)            // 131072 (g bank + o bank)
#define SMH_OFF   (SMW_BYTES)
#define SMEM_DYN  (SMH_OFF + 4096)             // 135168 bytes (< 227KB limit)

// ---------------- device scratch (no allocations allowed) ----------------
__device__ float g_bias[4][NG];          // b_ih + b_hh per layer
__device__ float g_pre[TT * NG];         // per-layer precomputed ih gates (+bias), 8.4MB
__device__ float g_hsA[TT * NH];         // ping-pong hidden-sequence buffers (fp32, GEMM food)
__device__ float g_hsB[TT * NH];
__device__ unsigned g_flags[GRID * 32];  // per-block barrier flags, 128B apart;
                                         // 256 parity flips/launch (even) -> replay-safe
__device__ unsigned short g_hq8[2][NH];  // packed h int8 (q1 | q2<<8), parity double-buffer

// dual-int8 hh weights, all 4 layers. Row layout (4096B): bytes[0,2048)=q1 planes
// packed 4/int32, bytes[2048,4096)=q2. W = (m/127)*(q1 + q2/254), per-row max m.
__device__ unsigned char q8_hh[(size_t)4 * NG * 4096];   // 134 MB
__device__ float s_hh[4 * NG];           // per-row raw max m

// HW tanh (max err ~1e-5); sigmoid via exact identity
__device__ __forceinline__ float tanh_fast(float x) {
    float y;
    asm("tanh.approx.f32 %0, %1;" : "=f"(y) : "f"(x));
    return y;
}
__device__ __forceinline__ float sigf(float x) {
    return fmaf(0.5f, tanh_fast(0.5f * x), 0.5f);
}

// 12 dp4a: hi*hi -> ah ; hi*lo + lo*hi -> am  (lo*lo dropped, rel ~6e-5)
#define DP4ACC(ah, am, whi, wlo, hh, hl)                       \
    do {                                                       \
        ah = __dp4a((int)(whi).x, (int)(hh).x, ah);            \
        ah = __dp4a((int)(whi).y, (int)(hh).y, ah);            \
        ah = __dp4a((int)(whi).z, (int)(hh).z, ah);            \
        ah = __dp4a((int)(whi).w, (int)(hh).w, ah);            \
        am = __dp4a((int)(whi).x, (int)(hl).x, am);            \
        am = __dp4a((int)(whi).y, (int)(hl).y, am);            \
        am = __dp4a((int)(whi).z, (int)(hl).z, am);            \
        am = __dp4a((int)(whi).w, (int)(hl).w, am);            \
        am = __dp4a((int)(wlo).x, (int)(hh).x, am);            \
        am = __dp4a((int)(wlo).y, (int)(hh).y, am);            \
        am = __dp4a((int)(wlo).z, (int)(hh).z, am);            \
        am = __dp4a((int)(wlo).w, (int)(hh).w, am);            \
    } while (0)

// ---------------- prologue: summed biases ----------------
__global__ void bias_kernel(const float* __restrict__ bi0, const float* __restrict__ bh0,
                            const float* __restrict__ bir, const float* __restrict__ bhr) {
    int idx = blockIdx.x * blockDim.x + threadIdx.x;   // 4*NG threads
    if (idx < 4 * NG) {
        int l = idx >> 13;
        int r = idx & (NG - 1);
        float v = (l == 0) ? (bi0[r] + bh0[r])
                           : (bir[(size_t)(l - 1) * NG + r] + bhr[(size_t)(l - 1) * NG + r]);
        g_bias[l][r] = v;
    }
}

// ---------------- prologue: quantize the 4 hh matrices to dual-int8 ----------------
__global__ void quant_kernel(const float* __restrict__ whh0,
                             const float* __restrict__ whhr) {
    int gw   = (blockIdx.x * blockDim.x + threadIdx.x) >> 5;
    int lane = threadIdx.x & 31;
    int nw   = (gridDim.x * blockDim.x) >> 5;
    for (int r = gw; r < 4 * NG; r += nw) {
        int l  = r >> 13;
        int rr = r & (NG - 1);
        const float* src = (l == 0) ? whh0 + (size_t)rr * NH
                                    : whhr + ((size_t)(l - 1) * NG + rr) * NH;
        const float4* s4 = (const float4*)src;
        float m = 0.f;
        #pragma unroll 4
        for (int i = lane; i < KF4; i += 32) {
            float4 v = s4[i];
            m = fmaxf(m, fmaxf(fmaxf(fabsf(v.x), fabsf(v.y)), fmaxf(fabsf(v.z), fabsf(v.w))));
        }
        #pragma unroll
        for (int o = 16; o; o >>= 1) m = fmaxf(m, __shfl_xor_sync(0xffffffffu, m, o));
        float qs = (m > 0.f) ? 127.0f / m : 0.f;
        if (lane == 0) s_hh[r] = m;            // raw max; scale folded in epilogue
        int* d32 = (int*)(q8_hh + (size_t)r * 4096);
        #pragma unroll 4
        for (int i = lane; i < KF4; i += 32) {   // one int32 = 4 weights
            float4 v = s4[i];
            float x0 = v.x * qs, x1 = v.y * qs, x2 = v.z * qs, x3 = v.w * qs;
            int a0 = __float2int_rn(x0), a1 = __float2int_rn(x1);
            int a2 = __float2int_rn(x2), a3 = __float2int_rn(x3);
            int b0 = __float2int_rn((x0 - (float)a0) * 254.f);
            int b1 = __float2int_rn((x1 - (float)a1) * 254.f);
            int b2 = __float2int_rn((x2 - (float)a2) * 254.f);
            int b3 = __float2int_rn((x3 - (float)a3) * 254.f);
            d32[i]       = (a0 & 0xff) | ((a1 & 0xff) << 8) | ((a2 & 0xff) << 16) | ((a3 & 0xff) << 24);
            d32[512 + i] = (b0 & 0xff) | ((b1 & 0xff) << 8) | ((b2 & 0xff) << 16) | ((b3 & 0xff) << 24);
        }
    }
}

// ---------------- prologue: g_pre[t][r] = bias0[r] for all t (layer0 default) -------
__global__ void prefill_kernel() {
    int t = blockIdx.x;
    for (int r = threadIdx.x; r < NG; r += blockDim.x)
        g_pre[(size_t)t * NG + r] = g_bias[0][r];
}

// ---------------- prologue: overwrite t=0 with z @ W_ih0^T + bias0 ----------------
__global__ void pre0_kernel(const float* __restrict__ wih0, const float* __restrict__ z) {
    int gw   = (blockIdx.x * blockDim.x + threadIdx.x) >> 5;
    int lane = threadIdx.x & 31;
    int nw   = (gridDim.x * blockDim.x) >> 5;
    for (int row = gw; row < NG; row += nw) {
        const float* wr = wih0 + (size_t)row * NZ;
        float s = 0.f;
        for (int k = lane; k < NZ; k += 32) s += wr[k] * z[k];
        #pragma unroll
        for (int o = 16; o; o >>= 1) s += __shfl_xor_sync(0xffffffffu, s, o);
        if (lane == 0) g_pre[row] = s + g_bias[0][row];
    }
}

// ---------------- per-layer ih GEMM: pre[t][row] = X[t]·W[row] + bias[row] ----------
#define GBK 16
__global__ void __launch_bounds__(256, 1)
gemm_pre_kernel(const float* __restrict__ X,
                const float* __restrict__ Wf,
                const float* __restrict__ bias) {
    __shared__ float Xs[GBK][132];
    __shared__ float Ws[GBK][132];
    const int tid = threadIdx.x;
    const int rb  = blockIdx.x * 128;
    const int tb  = blockIdx.y * 128;
    const int tx  = tid & 15, ty = tid >> 4;

    float acc[8][8];
    #pragma unroll
    for (int i = 0; i < 8; ++i)
        #pragma unroll
        for (int j = 0; j < 8; ++j) acc[i][j] = 0.f;

    float4 px[2], pw[2];
    #pragma unroll
    for (int r = 0; r < 2; ++r) {
        int idx = tid + r * 256;
        int tt  = idx >> 2;
        int k4  = idx & 3;
        px[r] = *(const float4*)(X  + (size_t)(tb + tt) * NH + k4 * 4);
        pw[r] = *(const float4*)(Wf + (size_t)(rb + tt) * NH + k4 * 4);
    }

    for (int kk = 0; kk < NH; kk += GBK) {
        __syncthreads();
        #pragma unroll
        for (int r = 0; r < 2; ++r) {
            int idx = tid + r * 256;
            int tt  = idx >> 2;
            int k0  = (idx & 3) * 4;
            Xs[k0 + 0][tt] = px[r].x; Xs[k0 + 1][tt] = px[r].y;
            Xs[k0 + 2][tt] = px[r].z; Xs[k0 + 3][tt] = px[r].w;
            Ws[k0 + 0][tt] = pw[r].x; Ws[k0 + 1][tt] = pw[r].y;
            Ws[k0 + 2][tt] = pw[r].z; Ws[k0 + 3][tt] = pw[r].w;
        }
        __syncthreads();
        if (kk + GBK < NH) {
            #pragma unroll
            for (int r = 0; r < 2; ++r) {
                int idx = tid + r * 256;
                int tt  = idx >> 2;
                int k4  = idx & 3;
                px[r] = *(const float4*)(X  + (size_t)(tb + tt) * NH + kk + GBK + k4 * 4);
                pw[r] = *(const float4*)(Wf + (size_t)(rb + tt) * NH + kk + GBK + k4 * 4);
            }
        }
        #pragma unroll
        for (int k = 0; k < GBK; ++k) {
            float4 x0 = *(const float4*)&Xs[k][ty * 8];
            float4 x1 = *(const float4*)&Xs[k][ty * 8 + 4];
            float4 w0 = *(const float4*)&Ws[k][tx * 8];
            float4 w1 = *(const float4*)&Ws[k][tx * 8 + 4];
            float xr[8] = {x0.x, x0.y, x0.z, x0.w, x1.x, x1.y, x1.z, x1.w};
            float wr[8] = {w0.x, w0.y, w0.z, w0.w, w1.x, w1.y, w1.z, w1.w};
            #pragma unroll
            for (int i = 0; i < 8; ++i)
                #pragma unroll
                for (int j = 0; j < 8; ++j)
                    acc[i][j] = fmaf(xr[i], wr[j], acc[i][j]);
        }
    }

    const float4 b0 = *(const float4*)&bias[rb + tx * 8];
    const float4 b1 = *(const float4*)&bias[rb + tx * 8 + 4];
    #pragma unroll
    for (int i = 0; i < 8; ++i) {
        float* cp = g_pre + (size_t)(tb + ty * 8 + i) * NG + rb + tx * 8;
        float4 v0 = make_float4(acc[i][0] + b0.x, acc[i][1] + b0.y,
                                acc[i][2] + b0.z, acc[i][3] + b0.w);
        float4 v1 = make_float4(acc[i][4] + b1.x, acc[i][5] + b1.y,
                                acc[i][6] + b1.z, acc[i][7] + b1.w);
        *(float4*)cp       = v0;
        *(float4*)(cp + 4) = v1;
    }
}

// ---------------- symmetric all-poll-all grid barrier (one hop, no atomics) ---------
// Each block release-stores its OWN flag (128 independent L2 lines -> parallel
// arrival, no single-address atomic serialization). Every block then polls ALL
// 128 flags itself (threads 0..127, ld.relaxed) -- no block-0 aggregation, no
// broadcast hop. Release orders the preceding st.global.cg h-stores at L2; polls
// and h reads are L2-direct, so observing the new flag implies the new h.
__device__ __forceinline__ void grid_barrier(unsigned& sense) {
    unsigned s = sense ^ 1u;
    sense = s;
    __syncthreads();                       // all warps' h stores issued
    if (threadIdx.x == 0)
        asm volatile("st.release.gpu.global.u32 [%0], %1;"
                     :: "l"(&g_flags[blockIdx.x * 32]), "r"(s) : "memory");
    if (threadIdx.x < GRID) {
        unsigned v;
        do {
            asm volatile("ld.relaxed.gpu.global.u32 %0, [%1];"
                         : "=r"(v) : "l"(&g_flags[threadIdx.x * 32]) : "memory");
        } while (v != s);
    }
    __syncthreads();                       // all flags observed by this block
}

// ---------------- per-layer persistent step kernel (dual-int8 dp4a) ----------------
// 128 blocks x 512 threads; one warp = one full hidden unit. 128 regs/thread.
// Gate routing: i,f -> REGISTERS (64 regs/lane); g,o -> SMEM (128KB, preloaded).
// h carried between steps as packed int8 pairs in g_hq8 (parity double-buffered).
__global__ void __launch_bounds__(PBLOCK, 1)
lstm_layer_kernel(const unsigned char* __restrict__ Wq,  // layer q8 base
                  const float* __restrict__ scl,         // per-row raw max [NG]
                  float* __restrict__ out) {             // [TT][NH] fp32 hidden out
    extern __shared__ char smem_dyn[];
    uint4* smW    = (uint4*)smem_dyn;                    // [2*SMW_U4]: g bank, o bank
    int*   smh_hi = (int*)(smem_dyn + SMH_OFF);          // [512] packed q1 of h
    int*   smh_lo = smh_hi + 512;                        // [512] packed q2 of h

    const int tid  = threadIdx.x;
    const int lane = tid & 31;
    const int widx = tid >> 5;        // 0..15 = unit within block
    const int u    = blockIdx.x * UPB + widx;
    const uint4* W = (const uint4*)Wq + (size_t)u * KQ4;

    // preload gate-g (index 2) and gate-o (index 3) q8 rows into SMEM
    {
        const uint4* Wg = (const uint4*)Wq + (size_t)2 * GSQ;
        const uint4* Wo = (const uint4*)Wq + (size_t)3 * GSQ;
        for (int i = tid; i < SMW_U4; i += PBLOCK) {
            int unit = i >> 8;                  // /KQ4
            int j    = i & (KQ4 - 1);
            size_t off = (size_t)(blockIdx.x * UPB + unit) * KQ4 + j;
            smW[i]          = __ldcg(Wg + off);
            smW[SMW_U4 + i] = __ldcg(Wo + off);
        }
    }
    const uint4* smWg = smW + widx * KQ4;            // this warp's gate-g row
    const uint4* smWo = smW + SMW_U4 + widx * KQ4;   // this warp's gate-o row

    // gates i,f -> registers: 16 x uint4 per lane (64 regs), loaded once per layer
    uint4 wih[4], wil[4], wfh[4], wfl[4];
    #pragma unroll
    for (int it = 0; it < 4; ++it) {
        const int j = lane + it * 32;
        wih[it] = __ldcg(W + j);
        wil[it] = __ldcg(W + 128 + j);
        wfh[it] = __ldcg(W + GSQ + j);
        wfl[it] = __ldcg(W + GSQ + 128 + j);
    }

    // dequant scales folded with 1/127^2 (W plane); h scale 1/127 folded too
    const float fold = 1.f / 16129.f;          // 1/(127*127)
    const float sc0 = scl[u]          * fold;
    const float sc1 = scl[NH + u]     * fold;
    const float sc2 = scl[2 * NH + u] * fold;
    const float sc3 = scl[3 * NH + u] * fold;

    unsigned sense = 0;
    float c = 0.f;                    // cell state (lane 0)

    for (int t = 0; t < TT; ++t) {
        float p0 = 0.f, p1 = 0.f, p2 = 0.f, p3 = 0.f;
        if (lane == 0) {
            const float* pt = g_pre + (size_t)t * NG;
            p0 = __ldcg(pt + u);
            p1 = __ldcg(pt + NH + u);
            p2 = __ldcg(pt + 2 * NH + u);
            p3 = __ldcg(pt + 3 * NH + u);
        }
        // stage h_{t-1} int8: 512 threads, one int2 (4 packed shorts) each
        if (t > 0) {
            const int2* src = (const int2*)g_hq8[(t - 1) & 1];
            int2 v = __ldcg(src + tid);
            smh_hi[tid] = __byte_perm(v.x, v.y, 0x6420);   // q1 bytes
            smh_lo[tid] = __byte_perm(v.x, v.y, 0x7531);   // q2 bytes
        } else {
            smh_hi[tid] = 0;
            smh_lo[tid] = 0;
        }
        __syncthreads();   // also covers smW preload before first use

        int ah0 = 0, am0 = 0, ah1 = 0, am1 = 0;
        int ah2 = 0, am2 = 0, ah3 = 0, am3 = 0;
        const uint4* Hhi4 = (const uint4*)smh_hi;
        const uint4* Hlo4 = (const uint4*)smh_lo;
        #pragma unroll
        for (int it = 0; it < 4; ++it) {
            const int j = lane + it * 32;        // 0..127
            const uint4 hh = Hhi4[j];
            const uint4 hl = Hlo4[j];
            DP4ACC(ah0, am0, wih[it], wil[it], hh, hl);    // gate i (registers)
            DP4ACC(ah1, am1, wfh[it], wfl[it], hh, hl);    // gate f (registers)
            uint4 w = smWg[j];
            uint4 x = smWg[128 + j];                       // gate g (SMEM)
            DP4ACC(ah2, am2, w, x, hh, hl);
            w = smWo[j];
            x = smWo[128 + j];                             // gate o (SMEM)
            DP4ACC(ah3, am3, w, x, hh, hl);
        }

        float d0 = fmaf((float)am0, 1.f / 254.f, (float)ah0);
        float d1 = fmaf((float)am1, 1.f / 254.f, (float)ah1);
        float d2 = fmaf((float)am2, 1.f / 254.f, (float)ah2);
        float d3 = fmaf((float)am3, 1.f / 254.f, (float)ah3);
        #pragma unroll
        for (int o = 16; o; o >>= 1) {
            d0 += __shfl_xor_sync(0xffffffffu, d0, o);
            d1 += __shfl_xor_sync(0xffffffffu, d1, o);
            d2 += __shfl_xor_sync(0xffffffffu, d2, o);
            d3 += __shfl_xor_sync(0xffffffffu, d3, o);
        }

        if (lane == 0) {
            float ig = fmaf(d0, sc0, p0);
            float fg = fmaf(d1, sc1, p1);
            float gg = fmaf(d2, sc2, p2);
            float og = fmaf(d3, sc3, p3);
            c = sigf(fg) * c + sigf(ig) * tanh_fast(gg);
            float h = sigf(og) * tanh_fast(c);
            out[(size_t)t * NH + u] = h;
            // quantize h for the next step: h in (-1,1) -> q1 + q2/254 over /127
            float x = h * 127.f;
            int q1 = __float2int_rn(x);
            int q2 = __float2int_rn((x - (float)q1) * 254.f);
            unsigned short pk = (unsigned short)((q1 & 0xff) | ((q2 & 0xff) << 8));
            unsigned short* hp = &g_hq8[t & 1][u];
            asm volatile("st.global.cg.u16 [%0], %1;" :: "l"(hp), "h"(pk) : "memory");
        }

        grid_barrier(sense);   // 256 flips per launch (even parity: replay-safe)
    }
}

// ---------------- epilogue: states[t] = h3[t] @ w_sp^T + b_sp ----------------
__global__ void proj_kernel(const float* __restrict__ wsp, const float* __restrict__ bsp,
                            float* __restrict__ out) {
    __shared__ float4 shh[KF4];
    const int t = blockIdx.x;
    const int tid = threadIdx.x;    // 256 threads
    const float4* h4 = (const float4*)g_hsB + (size_t)t * KF4;  // layer3 output in B
    shh[tid]       = h4[tid];
    shh[tid + 256] = h4[tid + 256];
    __syncthreads();
    const int widx = tid >> 5, lane = tid & 31;
    for (int o = widx; o < 64; o += 8) {
        const float4* wr = (const float4*)wsp + (size_t)o * KF4;
        float s = 0.f;
        #pragma unroll 4
        for (int i = lane; i < KF4; i += 32) {
            float4 w = __ldg(wr + i);
            float4 hv = shh[i];
            s += w.x * hv.x + w.y * hv.y + w.z * hv.z + w.w * hv.w;
        }
        #pragma unroll
        for (int off = 16; off; off >>= 1) s += __shfl_xor_sync(0xffffffffu, s, off);
        if (lane == 0) out[(size_t)t * 64 + o] = s + bsp[o];
    }
}

// ---------------- launch ----------------
extern "C" void kernel_launch(void* const* d_in, const int* in_sizes, int n_in,
                              void* d_out, int out_size) {
    const float* z      = (const float*)d_in[0];
    const float* w_ih0  = (const float*)d_in[1];
    const float* w_hh0  = (const float*)d_in[2];
    const float* b_ih0  = (const float*)d_in[3];
    const float* b_hh0  = (const float*)d_in[4];
    const float* w_ih_r = (const float*)d_in[5];
    const float* w_hh_r = (const float*)d_in[6];
    const float* b_ih_r = (const float*)d_in[7];
    const float* b_hh_r = (const float*)d_in[8];
    const float* w_sp   = (const float*)d_in[9];
    const float* b_sp   = (const float*)d_in[10];
    float* out = (float*)d_out;

    static unsigned char* q8_p = nullptr;
    static float* s_hh_p = nullptr;
    static float* bias_p = nullptr;
    static float* hsA_p = nullptr;
    static float* hsB_p = nullptr;
    if (!q8_p) {
        cudaGetSymbolAddress((void**)&q8_p, q8_hh);
        cudaGetSymbolAddress((void**)&s_hh_p, s_hh);
        cudaGetSymbolAddress((void**)&bias_p, g_bias);
        cudaGetSymbolAddress((void**)&hsA_p, g_hsA);
        cudaGetSymbolAddress((void**)&hsB_p, g_hsB);
        cudaFuncSetAttribute(lstm_layer_kernel,
                             cudaFuncAttributeMaxDynamicSharedMemorySize, SMEM_DYN);
        cudaFuncSetAttribute(lstm_layer_kernel,
                             cudaFuncAttributePreferredSharedMemoryCarveout, 60);
    }

    dim3 ggrid(NG / 128, TT / 128);   // 64 x 2 = 128 blocks (one wave)

    bias_kernel<<<64, 512>>>(b_ih0, b_hh0, b_ih_r, b_hh_r);
    quant_kernel<<<448, 512>>>(w_hh0, w_hh_r);
    prefill_kernel<<<TT, 1024>>>();
    pre0_kernel<<<128, 256>>>(w_ih0, z);

    const size_t LQ = (size_t)NG * 4096;   // bytes per layer of q8 weights

    // layer 0 -> hsA
    lstm_layer_kernel<<<GRID, PBLOCK, SMEM_DYN>>>(q8_p, s_hh_p, hsA_p);
    // layer 1: pre = hsA @ w_ih_r[0]^T + bias1 ; -> hsB
    gemm_pre_kernel<<<ggrid, 256>>>(hsA_p, w_ih_r, bias_p + 1 * NG);
    lstm_layer_kernel<<<GRID, PBLOCK, SMEM_DYN>>>(q8_p + 1 * LQ, s_hh_p + 1 * NG, hsB_p);
    // layer 2
    gemm_pre_kernel<<<ggrid, 256>>>(hsB_p, w_ih_r + (size_t)1 * NG * NH, bias_p + 2 * NG);
    lstm_layer_kernel<<<GRID, PBLOCK, SMEM_DYN>>>(q8_p + 2 * LQ, s_hh_p + 2 * NG, hsA_p);
    // layer 3
    gemm_pre_kernel<<<ggrid, 256>>>(hsA_p, w_ih_r + (size_t)2 * NG * NH, bias_p + 3 * NG);
    lstm_layer_kernel<<<GRID, PBLOCK, SMEM_DYN>>>(q8_p + 3 * LQ, s_hh_p + 3 * NG, hsB_p);

    proj_kernel<<<TT, 256>>>(w_sp, b_sp, out);
}